// round 13
// baseline (speedup 1.0000x reference)
#include <cuda_runtime.h>
#include <cuda_bf16.h>
#include <mma.h>
#include <cstdint>
#include <math.h>

using namespace nvcuda;

// Problem constants
#define NA  1024   // N atoms
#define EE  8192   // E edges
#define MM  8192   // M envelope table
#define BB  64     // B batches
#define INC 512    // IN_CH
#define HC  1024   // H_CH
#define NH  8      // heads
#define HD  128    // head dim

#define SEG 524288 // elements per split slab (all 7 external operands are 512K elems)

// ---------------- scratch ----------------
__device__ __nv_bfloat16 g_split_h[7 * SEG];     // q,k,v,Wq,Wk,Wv,Wo (hi)
__device__ __nv_bfloat16 g_split_l[7 * SEG];     // (lo)
__device__ __nv_bfloat16 g_ph[3 * NA * HC];      // qp/kp/vp hi
__device__ __nv_bfloat16 g_pl[3 * NA * HC];      // qp/kp/vp lo
__device__ __nv_bfloat16 g_lnh[NA * HC];
__device__ __nv_bfloat16 g_lnl[NA * HC];
__device__ __nv_bfloat16 g_W2h[(size_t)NH * NA * NA];
__device__ __nv_bfloat16 g_W2l[(size_t)NH * NA * NA];
__device__ float g_EB[(size_t)MM * NA];          // exp(attn_bias^T)[m][n]
__device__ float g_ES0[(size_t)NH * NA * NA];    // exp(S0)[h][a][n]
__device__ float g_C[BB * NH * NA];
__device__ float g_attn[NA * HC];
__device__ int   g_seg[BB + 1];
__device__ int   g_off[NA + 1];
__device__ int   g_csr[EE];

__device__ __forceinline__ void split2(float v, __nv_bfloat16& h, __nv_bfloat16& l) {
    h = __float2bfloat16(v);
    l = __float2bfloat16(v - __bfloat162float(h));
}

__device__ __forceinline__ uint32_t smem_u32(const void* p) {
    return (uint32_t)__cvta_generic_to_shared(p);
}
__device__ __forceinline__ void cp16(uint32_t dst, const void* src) {
    asm volatile("cp.async.cg.shared.global [%0], [%1], 16;" :: "r"(dst), "l"(src));
}
#define CP_COMMIT asm volatile("cp.async.commit_group;" ::: "memory")

// ---------------- split the 7 external fp32 operands into hi/lo bf16 ----------------
__global__ void __launch_bounds__(256) split_kernel(
    const float* __restrict__ q,  const float* __restrict__ k,  const float* __restrict__ v,
    const float* __restrict__ Wq, const float* __restrict__ Wk, const float* __restrict__ Wv,
    const float* __restrict__ Wo)
{
    const float* srcs[7] = {q, k, v, Wq, Wk, Wv, Wo};
    const float* s = srcs[blockIdx.y];
    const size_t base = (size_t)blockIdx.y * SEG;
    const int i0 = (blockIdx.x * 256 + threadIdx.x) * 4;
    float4 f = *(const float4*)(s + i0);
    union { __nv_bfloat16 b[4]; uint2 u; } H, L;
    split2(f.x, H.b[0], L.b[0]);
    split2(f.y, H.b[1], L.b[1]);
    split2(f.z, H.b[2], L.b[2]);
    split2(f.w, H.b[3], L.b[3]);
    *(uint2*)(g_split_h + base + i0) = H.u;
    *(uint2*)(g_split_l + base + i0) = L.u;
}

// ================= pipelined wmma GEMM cores =================
// Split bf16: C += Ah@Bh^T + Ah@Bl^T + Al@Bh^T  (fp32 accum), K chunk 32, 2 stages.
typedef wmma::fragment<wmma::accumulator, 16, 16, 16, float> FragC;

// ---- rr: A [M,K] row-major (M tile 128), B [N,K] row-major (N tile NT) ----
template<int NT>
__device__ __forceinline__ void rr_load(
    const __nv_bfloat16* __restrict__ Ah, const __nv_bfloat16* __restrict__ Al, int lda, int m0,
    const __nv_bfloat16* __restrict__ Bh, const __nv_bfloat16* __restrict__ Bl, int ldb, int n0,
    int k0, uint32_t stage)
{
    const int tid = threadIdx.x;
#pragma unroll
    for (int rep = 0; rep < 2; rep++) {
        int idx = tid + rep * 256;             // 512 chunks: 128 rows x 4
        int r = idx >> 2, c8 = (idx & 3) * 8;
        uint32_t d = stage + (uint32_t)(r * 40 + c8) * 2;
        size_t off = (size_t)(m0 + r) * lda + k0 + c8;
        cp16(d, Ah + off);
        cp16(d + 10240, Al + off);
    }
#pragma unroll
    for (int rep = 0; rep < NT / 64; rep++) {
        int idx = tid + rep * 256;
        int r = idx >> 2, c8 = (idx & 3) * 8;
        uint32_t d = stage + 20480 + (uint32_t)(r * 40 + c8) * 2;
        size_t off = (size_t)(n0 + r) * ldb + k0 + c8;
        cp16(d, Bh + off);
        cp16(d + NT * 80, Bl + off);
    }
}

template<int NT>
__device__ __forceinline__ void rr_compute(const char* st, FragC (&c)[2][NT / 32])
{
    const int wid = threadIdx.x >> 5;
    const int wm0 = (wid >> 1) * 32;
    const int wn0 = (wid & 1) * (NT / 2);
    const __nv_bfloat16* sAh = (const __nv_bfloat16*)st;
    const __nv_bfloat16* sAl = sAh + 128 * 40;
    const __nv_bfloat16* sBh = (const __nv_bfloat16*)(st + 20480);
    const __nv_bfloat16* sBl = sBh + NT * 40;
    constexpr int FN = NT / 32;
#pragma unroll
    for (int kk = 0; kk < 32; kk += 16) {
        wmma::fragment<wmma::matrix_a, 16, 16, 16, __nv_bfloat16, wmma::row_major> aH[2], aL[2];
        wmma::fragment<wmma::matrix_b, 16, 16, 16, __nv_bfloat16, wmma::col_major> bH[FN], bL[FN];
#pragma unroll
        for (int i = 0; i < 2; i++) {
            wmma::load_matrix_sync(aH[i], sAh + (wm0 + 16 * i) * 40 + kk, 40);
            wmma::load_matrix_sync(aL[i], sAl + (wm0 + 16 * i) * 40 + kk, 40);
        }
#pragma unroll
        for (int j = 0; j < FN; j++) {
            wmma::load_matrix_sync(bH[j], sBh + (wn0 + 16 * j) * 40 + kk, 40);
            wmma::load_matrix_sync(bL[j], sBl + (wn0 + 16 * j) * 40 + kk, 40);
        }
#pragma unroll
        for (int i = 0; i < 2; i++)
#pragma unroll
            for (int j = 0; j < FN; j++) {
                wmma::mma_sync(c[i][j], aH[i], bH[j], c[i][j]);
                wmma::mma_sync(c[i][j], aH[i], bL[j], c[i][j]);
                wmma::mma_sync(c[i][j], aL[i], bH[j], c[i][j]);
            }
    }
}

template<int NT>
__device__ __forceinline__ void gemm_rr_pipe(
    const __nv_bfloat16* Ah, const __nv_bfloat16* Al, int lda, int m0,
    const __nv_bfloat16* Bh, const __nv_bfloat16* Bl, int ldb, int n0,
    int K, char* smem, FragC (&c)[2][NT / 32])
{
    const int SSTR = 20480 + NT * 160;
    uint32_t sb = smem_u32(smem);
#pragma unroll
    for (int i = 0; i < 2; i++)
#pragma unroll
        for (int j = 0; j < NT / 32; j++) wmma::fill_fragment(c[i][j], 0.f);
    rr_load<NT>(Ah, Al, lda, m0, Bh, Bl, ldb, n0, 0, sb);
    CP_COMMIT;
    const int NC = K / 32;
    for (int ch = 0; ch < NC; ch++) {
        if (ch + 1 < NC) {
            rr_load<NT>(Ah, Al, lda, m0, Bh, Bl, ldb, n0, (ch + 1) * 32,
                        sb + ((ch + 1) & 1) * SSTR);
            CP_COMMIT;
            asm volatile("cp.async.wait_group 1;" ::: "memory");
        } else {
            asm volatile("cp.async.wait_group 0;" ::: "memory");
        }
        __syncthreads();
        rr_compute<NT>(smem + (ch & 1) * SSTR, c);
        __syncthreads();
    }
}

// ---- kk: A [K,M] K-major (M tile 128), B [K,N] K-major (N tile 64) ----
__device__ __forceinline__ void kk_load(
    const __nv_bfloat16* __restrict__ Ah, const __nv_bfloat16* __restrict__ Al, int lda, int m0,
    const __nv_bfloat16* __restrict__ Bh, const __nv_bfloat16* __restrict__ Bl, int ldb, int n0,
    int k0, uint32_t stage)
{
    const int tid = threadIdx.x;
#pragma unroll
    for (int rep = 0; rep < 2; rep++) {
        int idx = tid + rep * 256;              // 512 chunks: 32 rows x 16
        int r = idx >> 4, c8 = (idx & 15) * 8;
        uint32_t d = stage + (uint32_t)(r * 136 + c8) * 2;
        size_t off = (size_t)(k0 + r) * lda + m0 + c8;
        cp16(d, Ah + off);
        cp16(d + 8704, Al + off);
    }
    {
        int r = tid >> 3, c8 = (tid & 7) * 8;   // 256 chunks: 32 rows x 8
        uint32_t d = stage + 17408 + (uint32_t)(r * 72 + c8) * 2;
        size_t off = (size_t)(k0 + r) * ldb + n0 + c8;
        cp16(d, Bh + off);
        cp16(d + 4608, Bl + off);
    }
}

__device__ __forceinline__ void kk_compute(const char* st, FragC (&c)[2][2])
{
    const int wid = threadIdx.x >> 5;
    const int wm0 = (wid >> 1) * 32;
    const int wn0 = (wid & 1) * 32;
    const __nv_bfloat16* sAh = (const __nv_bfloat16*)st;
    const __nv_bfloat16* sAl = sAh + 32 * 136;
    const __nv_bfloat16* sBh = (const __nv_bfloat16*)(st + 17408);
    const __nv_bfloat16* sBl = sBh + 32 * 72;
#pragma unroll
    for (int kk = 0; kk < 32; kk += 16) {
        wmma::fragment<wmma::matrix_a, 16, 16, 16, __nv_bfloat16, wmma::col_major> aH[2], aL[2];
        wmma::fragment<wmma::matrix_b, 16, 16, 16, __nv_bfloat16, wmma::row_major> bH[2], bL[2];
#pragma unroll
        for (int i = 0; i < 2; i++) {
            wmma::load_matrix_sync(aH[i], sAh + kk * 136 + wm0 + 16 * i, 136);
            wmma::load_matrix_sync(aL[i], sAl + kk * 136 + wm0 + 16 * i, 136);
        }
#pragma unroll
        for (int j = 0; j < 2; j++) {
            wmma::load_matrix_sync(bH[j], sBh + kk * 72 + wn0 + 16 * j, 72);
            wmma::load_matrix_sync(bL[j], sBl + kk * 72 + wn0 + 16 * j, 72);
        }
#pragma unroll
        for (int i = 0; i < 2; i++)
#pragma unroll
            for (int j = 0; j < 2; j++) {
                wmma::mma_sync(c[i][j], aH[i], bH[j], c[i][j]);
                wmma::mma_sync(c[i][j], aH[i], bL[j], c[i][j]);
                wmma::mma_sync(c[i][j], aL[i], bH[j], c[i][j]);
            }
    }
}

__device__ __forceinline__ void gemm_kk_pipe(
    const __nv_bfloat16* Ah, const __nv_bfloat16* Al, int lda, int m0,
    const __nv_bfloat16* Bh, const __nv_bfloat16* Bl, int ldb, int n0,
    int K, char* smem, FragC (&c)[2][2])
{
    const int SSTR = 26624;
    uint32_t sb = smem_u32(smem);
#pragma unroll
    for (int i = 0; i < 2; i++)
#pragma unroll
        for (int j = 0; j < 2; j++) wmma::fill_fragment(c[i][j], 0.f);
    kk_load(Ah, Al, lda, m0, Bh, Bl, ldb, n0, 0, sb);
    CP_COMMIT;
    const int NC = K / 32;
    for (int ch = 0; ch < NC; ch++) {
        if (ch + 1 < NC) {
            kk_load(Ah, Al, lda, m0, Bh, Bl, ldb, n0, (ch + 1) * 32,
                    sb + ((ch + 1) & 1) * SSTR);
            CP_COMMIT;
            asm volatile("cp.async.wait_group 1;" ::: "memory");
        } else {
            asm volatile("cp.async.wait_group 0;" ::: "memory");
        }
        __syncthreads();
        kk_compute(smem + (ch & 1) * SSTR, c);
        __syncthreads();
    }
}

// epilogue scratch overlay: per warp 32 x (WN+4) floats on top of pipeline smem
template<int WN, int FN>
__device__ __forceinline__ float* epi_store(FragC (&c)[2][FN], char* smem, int wid)
{
    float* sC = (float*)smem + wid * 32 * (WN + 4);
#pragma unroll
    for (int i = 0; i < 2; i++)
#pragma unroll
        for (int j = 0; j < FN; j++)
            wmma::store_matrix_sync(sC + i * 16 * (WN + 4) + j * 16, c[i][j],
                                    WN + 4, wmma::mem_row_major);
    __syncwarp();
    return sC;
}

// ---- qkv: proj_z[atom][hc] = in_z @ W_z^T + b_z, written as hi/lo bf16 ----
__global__ void __launch_bounds__(256) qkv_wmma(
    const float* __restrict__ bq, const float* __restrict__ bk, const float* __restrict__ bv)
{
    extern __shared__ char smem[];
    const int tid = threadIdx.x, wid = tid >> 5, lane = tid & 31;
    const int z  = blockIdx.z;
    const int m0 = blockIdx.y * 128;   // atom
    const int n0 = blockIdx.x * 128;   // hc
    const float* bias = (z == 0) ? bq : (z == 1) ? bk : bv;
    FragC c[2][4];
    gemm_rr_pipe<128>(g_split_h + (size_t)z * SEG,       g_split_l + (size_t)z * SEG,       INC, m0,
                      g_split_h + (size_t)(3 + z) * SEG, g_split_l + (size_t)(3 + z) * SEG, INC, n0,
                      INC, smem, c);
    float* sC = epi_store<64, 4>(c, smem, wid);
    const int wm0 = (wid >> 1) * 32, wn0 = (wid & 1) * 64;
    const int atom = m0 + wm0 + lane;
    const size_t ob = (size_t)z * NA * HC + (size_t)atom * HC + n0 + wn0;
    union { __nv_bfloat16 b[8]; uint4 u; } H, L;
#pragma unroll
    for (int t = 0; t < 8; t++) {
#pragma unroll
        for (int e = 0; e < 8; e++) {
            float val = sC[lane * 68 + t * 8 + e] + bias[n0 + wn0 + t * 8 + e];
            split2(val, H.b[e], L.b[e]);
        }
        *(uint4*)(g_ph + ob + t * 8) = H.u;
        *(uint4*)(g_pl + ob + t * 8) = L.u;
    }
}

// ---- s0: ES0[h][a][n] = exp(dot(kp_a, qp_n)/sqrt(D)) ----
__global__ void __launch_bounds__(256) s0_wmma()
{
    extern __shared__ char smem[];
    const int tid = threadIdx.x, wid = tid >> 5, lane = tid & 31;
    const int h  = blockIdx.z;
    const int m0 = blockIdx.y * 128;   // a
    const int n0 = blockIdx.x * 128;   // n
    FragC c[2][4];
    gemm_rr_pipe<128>(g_ph + 1 * NA * HC + h * HD, g_pl + 1 * NA * HC + h * HD, HC, m0,
                      g_ph + 0 * NA * HC + h * HD, g_pl + 0 * NA * HC + h * HD, HC, n0,
                      HD, smem, c);
    float* sC = epi_store<64, 4>(c, smem, wid);
    const int wm0 = (wid >> 1) * 32, wn0 = (wid & 1) * 64;
    const int a = m0 + wm0 + lane;
    const float scale = 0.08838834764831845f;   // 1/sqrt(128)
    float* dst = g_ES0 + ((size_t)h * NA + a) * NA + n0 + wn0;
#pragma unroll
    for (int t = 0; t < 16; t++) {
        float4 r;
        r.x = __expf(sC[lane * 68 + t * 4 + 0] * scale);
        r.y = __expf(sC[lane * 68 + t * 4 + 1] * scale);
        r.z = __expf(sC[lane * 68 + t * 4 + 2] * scale);
        r.w = __expf(sC[lane * 68 + t * 4 + 3] * scale);
        *(float4*)(dst + t * 4) = r;
    }
}

// ---- out2: attn[n][h*HD+d] = sum_a W2[h][a][n] * vp[a][h*HD+d] ----
__global__ void __launch_bounds__(256) out2_wmma()
{
    extern __shared__ char smem[];
    const int tid = threadIdx.x, wid = tid >> 5, lane = tid & 31;
    const int h  = blockIdx.z;
    const int m0 = blockIdx.y * 128;   // n
    const int n0 = blockIdx.x * 64;    // d
    FragC c[2][2];
    gemm_kk_pipe(g_W2h + (size_t)h * NA * NA, g_W2l + (size_t)h * NA * NA, NA, m0,
                 g_ph + 2 * NA * HC + h * HD, g_pl + 2 * NA * HC + h * HD, HC, n0,
                 NA, smem, c);
    float* sC = epi_store<32, 2>(c, smem, wid);
    const int wm0 = (wid >> 1) * 32, wn0 = (wid & 1) * 32;
    const int n = m0 + wm0 + lane;
    float* dst = g_attn + (size_t)n * HC + h * HD + n0 + wn0;
#pragma unroll
    for (int t = 0; t < 8; t++) {
        float4 r;
        r.x = sC[lane * 36 + t * 4 + 0];
        r.y = sC[lane * 36 + t * 4 + 1];
        r.z = sC[lane * 36 + t * 4 + 2];
        r.w = sC[lane * 36 + t * 4 + 3];
        *(float4*)(dst + t * 4) = r;
    }
}

// ---- final: out[n][ic] = ln @ Wo^T + bo ----
__global__ void __launch_bounds__(256) final_wmma(
    const float* __restrict__ bo, float* __restrict__ out)
{
    extern __shared__ char smem[];
    const int tid = threadIdx.x, wid = tid >> 5, lane = tid & 31;
    const int m0 = blockIdx.y * 128;   // n
    const int n0 = blockIdx.x * 128;   // ic
    FragC c[2][4];
    gemm_rr_pipe<128>(g_lnh, g_lnl, HC, m0,
                      g_split_h + 6 * SEG, g_split_l + 6 * SEG, HC, n0,
                      HC, smem, c);
    float* sC = epi_store<64, 4>(c, smem, wid);
    const int wm0 = (wid >> 1) * 32, wn0 = (wid & 1) * 64;
    const int n = m0 + wm0 + lane;
    float* dst = out + (size_t)n * INC + n0 + wn0;
#pragma unroll
    for (int t = 0; t < 16; t++) {
        float4 r;
        r.x = sC[lane * 68 + t * 4 + 0] + bo[n0 + wn0 + t * 4 + 0];
        r.y = sC[lane * 68 + t * 4 + 1] + bo[n0 + wn0 + t * 4 + 1];
        r.z = sC[lane * 68 + t * 4 + 2] + bo[n0 + wn0 + t * 4 + 2];
        r.w = sC[lane * 68 + t * 4 + 3] + bo[n0 + wn0 + t * 4 + 3];
        *(float4*)(dst + t * 4) = r;
    }
}

// ---------------- EB[m][n] = exp(attn_bias[n][m]) — two n-tiles per CTA for ILP ------
__global__ void __launch_bounds__(256) transpose_exp(const float* __restrict__ src)
{
    __shared__ float t0[64][65], t1[64][65];
    const int m0 = blockIdx.x * 64, n0 = blockIdx.y * 128;
    const int tid = threadIdx.x;
    const int r = tid >> 4, c4 = (tid & 15) * 4;
#pragma unroll
    for (int p = 0; p < 4; p++) {
        const int row = n0 + r + p * 16;
        float4 f0 = *(const float4*)(src + (size_t)row * MM + m0 + c4);
        float4 f1 = *(const float4*)(src + (size_t)(row + 64) * MM + m0 + c4);
        t0[r + p * 16][c4 + 0] = f0.x; t0[r + p * 16][c4 + 1] = f0.y;
        t0[r + p * 16][c4 + 2] = f0.z; t0[r + p * 16][c4 + 3] = f0.w;
        t1[r + p * 16][c4 + 0] = f1.x; t1[r + p * 16][c4 + 1] = f1.y;
        t1[r + p * 16][c4 + 2] = f1.z; t1[r + p * 16][c4 + 3] = f1.w;
    }
    __syncthreads();
#pragma unroll
    for (int p = 0; p < 4; p++) {
        const int mloc = r + p * 16;
        float4 o0, o1;
        o0.x = __expf(t0[c4 + 0][mloc]); o0.y = __expf(t0[c4 + 1][mloc]);
        o0.z = __expf(t0[c4 + 2][mloc]); o0.w = __expf(t0[c4 + 3][mloc]);
        o1.x = __expf(t1[c4 + 0][mloc]); o1.y = __expf(t1[c4 + 1][mloc]);
        o1.z = __expf(t1[c4 + 2][mloc]); o1.w = __expf(t1[c4 + 3][mloc]);
        float* dst = g_EB + (size_t)(m0 + mloc) * NA + n0 + c4;
        *(float4*)dst = o0;
        *(float4*)(dst + 64) = o1;
    }
}

// ---------------- seg (binary search) + CSR histogram/scan, fused, 1 CTA ------------
__global__ void __launch_bounds__(1024) seg_hist_kernel(
    const int* __restrict__ batch_index, const int* __restrict__ atom_index)
{
    __shared__ int buf[1024];
    const int tid = threadIdx.x;
    if (tid <= BB) {
        int lo = 0, hi = EE;
        while (lo < hi) {
            int mid = (lo + hi) >> 1;
            if (batch_index[mid] < tid) lo = mid + 1; else hi = mid;
        }
        g_seg[tid] = lo;
    }
    buf[tid] = 0;
    __syncthreads();
#pragma unroll
    for (int i = 0; i < EE / 1024; i++)
        atomicAdd(&buf[atom_index[tid + i * 1024]], 1);
    __syncthreads();
    for (int s = 1; s < 1024; s <<= 1) {
        int v = (tid >= s) ? buf[tid - s] : 0;
        __syncthreads();
        buf[tid] += v;
        __syncthreads();
    }
    g_off[tid + 1] = buf[tid];
    if (tid == 0) g_off[0] = 0;
}

__global__ void __launch_bounds__(256) fill_kernel(const int* __restrict__ atom_index)
{
    const int w = (blockIdx.x * 256 + threadIdx.x) >> 5;
    const int lane = threadIdx.x & 31;
    int o = g_off[w];
    for (int base = 0; base < EE; base += 32) {
        int a = atom_index[base + lane];
        bool match = (a == w);
        unsigned mask = __ballot_sync(0xffffffffu, match);
        int rank = __popc(mask & ((1u << lane) - 1));
        if (match) g_csr[o + rank] = base + lane;
        o += __popc(mask);
    }
}

// ---- C[b][h][n] = 1 / (sum_{e in b} env_e * EB[mp_e][n] * ES0[h][a_e][n] + 1e-16) ----
// 2 n per thread, float2 loads
__global__ void __launch_bounds__(256) csum_kernel(
    const int* __restrict__ atom_index, const int* __restrict__ edge_map,
    const float* __restrict__ envelope)
{
    const int b = blockIdx.y;
    const int n = blockIdx.x * 512 + threadIdx.x * 2;
    const int s0 = g_seg[b], s1 = g_seg[b + 1];
    __shared__ int   s_a[128], s_mp[128];
    __shared__ float s_env[128];
    float2 acc[NH];
#pragma unroll
    for (int h = 0; h < NH; h++) { acc[h].x = 0.f; acc[h].y = 0.f; }
    for (int c = s0; c < s1; c += 128) {
        const int cnt = min(128, s1 - c);
        __syncthreads();
        if (threadIdx.x < 128 && threadIdx.x < cnt) {
            int e = c + threadIdx.x;
            int mp = edge_map[e];
            s_a[threadIdx.x]   = atom_index[e];
            s_mp[threadIdx.x]  = mp;
            s_env[threadIdx.x] = envelope[mp];
        }
        __syncthreads();
#pragma unroll 2
        for (int i = 0; i < cnt; i++) {
            float2 eb = *(const float2*)(g_EB + (size_t)s_mp[i] * NA + n);
            float ev = s_env[i];
            float2 val; val.x = ev * eb.x; val.y = ev * eb.y;
            const float* es = g_ES0 + (size_t)s_a[i] * NA + n;
#pragma unroll
            for (int h = 0; h < NH; h++) {
                float2 e2 = *(const float2*)(es + (size_t)h * NA * NA);
                acc[h].x += val.x * e2.x;
                acc[h].y += val.y * e2.y;
            }
        }
    }
#pragma unroll
    for (int h = 0; h < NH; h++) {
        float2 r;
        r.x = 1.f / (acc[h].x + 1e-16f);
        r.y = 1.f / (acc[h].y + 1e-16f);
        *(float2*)(g_C + ((size_t)b * NH + h) * NA + n) = r;
    }
}

// ---- W2[h][a][n] = ES0[h][a][n] * sum_{e->a} env_e^2 * EB[mp_e][n] * C[b_e][h][n] ----
// 2 n per thread, float2 loads
__global__ void __launch_bounds__(128) w2_kernel(
    const int* __restrict__ edge_map, const int* __restrict__ batch_index,
    const float* __restrict__ envelope)
{
    const int a = blockIdx.y;
    const int n = (blockIdx.x * 128 + threadIdx.x) * 2;
    const int o0 = g_off[a], o1 = g_off[a + 1];
    float2 acc[NH];
#pragma unroll
    for (int h = 0; h < NH; h++) { acc[h].x = 0.f; acc[h].y = 0.f; }
#pragma unroll 2
    for (int j = o0; j < o1; j++) {
        int e  = g_csr[j];
        int mp = edge_map[e];
        int bb = batch_index[e];
        float env = envelope[mp];
        float2 eb = *(const float2*)(g_EB + (size_t)mp * NA + n);
        float e2v = env * env;
        float2 t; t.x = e2v * eb.x; t.y = e2v * eb.y;
        const float* Cb = g_C + (size_t)bb * NH * NA + n;
#pragma unroll
        for (int h = 0; h < NH; h++) {
            float2 c2 = *(const float2*)(Cb + (size_t)h * NA);
            acc[h].x += t.x * c2.x;
            acc[h].y += t.y * c2.y;
        }
    }
#pragma unroll
    for (int h = 0; h < NH; h++) {
        const size_t idx = ((size_t)h * NA + a) * NA + n;
        float2 es = *(const float2*)(g_ES0 + idx);
        union { __nv_bfloat16 b[2]; uint32_t u; } H, L;
        split2(es.x * acc[h].x, H.b[0], L.b[0]);
        split2(es.y * acc[h].y, H.b[1], L.b[1]);
        *(uint32_t*)(g_W2h + idx) = H.u;
        *(uint32_t*)(g_W2l + idx) = L.u;
    }
}

// ---------------- LayerNorm -> hi/lo bf16 ----------------
__global__ void __launch_bounds__(256) ln_kernel(
    const float* __restrict__ ln_g, const float* __restrict__ ln_b)
{
    const int n = blockIdx.x;
    const int tid = threadIdx.x;
    const float* x = g_attn + (size_t)n * HC;
    float s = 0.f, s2 = 0.f;
    for (int i = tid; i < HC; i += 256) {
        float v = x[i];
        s += v; s2 += v * v;
    }
#pragma unroll
    for (int o = 16; o > 0; o >>= 1) {
        s  += __shfl_xor_sync(0xffffffffu, s, o);
        s2 += __shfl_xor_sync(0xffffffffu, s2, o);
    }
    __shared__ float ws[8], ws2[8], stats[2];
    if ((tid & 31) == 0) { ws[tid >> 5] = s; ws2[tid >> 5] = s2; }
    __syncthreads();
    if (tid == 0) {
        float a = 0.f, b = 0.f;
#pragma unroll
        for (int i = 0; i < 8; i++) { a += ws[i]; b += ws2[i]; }
        float mean = a * (1.f / HC);
        float var  = b * (1.f / HC) - mean * mean;
        stats[0] = mean;
        stats[1] = rsqrtf(var + 1e-7f);
    }
    __syncthreads();
    const float mean = stats[0], inv = stats[1];
    for (int i = tid; i < HC; i += 256) {
        float val = (x[i] - mean) * inv * ln_g[i] + ln_b[i];
        split2(val, g_lnh[(size_t)n * HC + i], g_lnl[(size_t)n * HC + i]);
    }
}

// ---------------- launch ----------------
extern "C" void kernel_launch(void* const* d_in, const int* in_sizes, int n_in,
                              void* d_out, int out_size)
{
    const float* q         = (const float*)d_in[0];
    const float* k         = (const float*)d_in[1];
    const float* v         = (const float*)d_in[2];
    const float* envelope  = (const float*)d_in[3];
    const float* attn_bias = (const float*)d_in[4];
    const float* Wq        = (const float*)d_in[5];
    const float* bq        = (const float*)d_in[6];
    const float* Wk        = (const float*)d_in[7];
    const float* bk        = (const float*)d_in[8];
    const float* Wv        = (const float*)d_in[9];
    const float* bv        = (const float*)d_in[10];
    const float* ln_g      = (const float*)d_in[11];
    const float* ln_b      = (const float*)d_in[12];
    const float* Wo        = (const float*)d_in[13];
    const float* bo        = (const float*)d_in[14];
    const int* atom_index  = (const int*)d_in[15];
    const int* batch_index = (const int*)d_in[16];
    const int* edge_map    = (const int*)d_in[17];
    float* out = (float*)d_out;

    const int SMEM_RR = 2 * (20480 + 128 * 160);   // 81920
    const int SMEM_KK = 2 * 26624;                 // 53248
    cudaFuncSetAttribute(qkv_wmma,   cudaFuncAttributeMaxDynamicSharedMemorySize, SMEM_RR);
    cudaFuncSetAttribute(s0_wmma,    cudaFuncAttributeMaxDynamicSharedMemorySize, SMEM_RR);
    cudaFuncSetAttribute(final_wmma, cudaFuncAttributeMaxDynamicSharedMemorySize, SMEM_RR);
    cudaFuncSetAttribute(out2_wmma,  cudaFuncAttributeMaxDynamicSharedMemorySize, SMEM_KK);

    // 1. split all external GEMM operands into hi/lo bf16
    split_kernel<<<dim3(SEG / 1024, 7), 256>>>(q, k, v, Wq, Wk, Wv, Wo);

    // 2. projections (tensor cores, split-bf16)
    qkv_wmma<<<dim3(HC / 128, NA / 128, 3), 256, SMEM_RR>>>(bq, bk, bv);

    // 3. EB = exp(attn_bias^T)
    transpose_exp<<<dim3(MM / 64, NA / 128), 256>>>(attn_bias);

    // 4. dense per-atom exp(scores)  [profiled launch]
    s0_wmma<<<dim3(NA / 128, NA / 128, NH), 256, SMEM_RR>>>();

    // 5-6. segment boundaries + CSR
    seg_hist_kernel<<<1, 1024>>>(batch_index, atom_index);
    fill_kernel<<<NA / 8, 256>>>(atom_index);

    // 7-8. softmax denominators + per-atom weights
    csum_kernel<<<dim3(NA / 512, BB), 256>>>(atom_index, edge_map, envelope);
    w2_kernel<<<dim3(NA / 256, NA), 128>>>(edge_map, batch_index, envelope);

    // 9. attention output (tensor cores)
    out2_wmma<<<dim3(HD / 64, NA / 128, NH), 256, SMEM_KK>>>();

    // 10. layernorm
    ln_kernel<<<NA, 256>>>(ln_g, ln_b);

    // 11. final projection (tensor cores)
    final_wmma<<<dim3(INC / 128, NA / 128), 256, SMEM_RR>>>(bo, out);
}

// round 14
// speedup vs baseline: 1.0935x; 1.0935x over previous
#include <cuda_runtime.h>
#include <cuda_bf16.h>
#include <mma.h>
#include <cstdint>
#include <math.h>

using namespace nvcuda;

// Problem constants
#define NA  1024   // N atoms
#define EE  8192   // E edges
#define MM  8192   // M envelope table
#define BB  64     // B batches
#define INC 512    // IN_CH
#define HC  1024   // H_CH
#define NH  8      // heads
#define HD  128    // head dim

#define SEG 524288 // elements per split slab (all 7 external operands are 512K elems)

// ---------------- scratch ----------------
__device__ __nv_bfloat16 g_split_h[7 * SEG];     // q,k,v,Wq,Wk,Wv,Wo (hi)
__device__ __nv_bfloat16 g_split_l[7 * SEG];     // (lo)
__device__ __nv_bfloat16 g_ph[3 * NA * HC];      // qp/kp/vp hi
__device__ __nv_bfloat16 g_pl[3 * NA * HC];      // qp/kp/vp lo
__device__ __nv_bfloat16 g_lnh[NA * HC];
__device__ __nv_bfloat16 g_lnl[NA * HC];
__device__ __nv_bfloat16 g_W2h[(size_t)NH * NA * NA];
__device__ __nv_bfloat16 g_W2l[(size_t)NH * NA * NA];
__device__ float g_EB[(size_t)MM * NA];          // exp(attn_bias^T)[m][n]
__device__ float g_ES0[(size_t)NH * NA * NA];    // exp(S0)[h][a][n]
__device__ float g_C[BB * NH * NA];
__device__ float g_attn[NA * HC];
__device__ int   g_seg[BB + 1];
__device__ int   g_off[NA + 1];
__device__ int   g_csr[EE];

__device__ __forceinline__ void split2(float v, __nv_bfloat16& h, __nv_bfloat16& l) {
    h = __float2bfloat16(v);
    l = __float2bfloat16(v - __bfloat162float(h));
}

__device__ __forceinline__ uint32_t smem_u32(const void* p) {
    return (uint32_t)__cvta_generic_to_shared(p);
}
__device__ __forceinline__ void cp16(uint32_t dst, const void* src) {
    asm volatile("cp.async.cg.shared.global [%0], [%1], 16;" :: "r"(dst), "l"(src));
}
#define CP_COMMIT asm volatile("cp.async.commit_group;" ::: "memory")

// ---------------- split the 7 external fp32 operands into hi/lo bf16 ----------------
__global__ void __launch_bounds__(256) split_kernel(
    const float* __restrict__ q,  const float* __restrict__ k,  const float* __restrict__ v,
    const float* __restrict__ Wq, const float* __restrict__ Wk, const float* __restrict__ Wv,
    const float* __restrict__ Wo)
{
    const float* srcs[7] = {q, k, v, Wq, Wk, Wv, Wo};
    const float* s = srcs[blockIdx.y];
    const size_t base = (size_t)blockIdx.y * SEG;
    const int i0 = (blockIdx.x * 256 + threadIdx.x) * 4;
    float4 f = *(const float4*)(s + i0);
    union { __nv_bfloat16 b[4]; uint2 u; } H, L;
    split2(f.x, H.b[0], L.b[0]);
    split2(f.y, H.b[1], L.b[1]);
    split2(f.z, H.b[2], L.b[2]);
    split2(f.w, H.b[3], L.b[3]);
    *(uint2*)(g_split_h + base + i0) = H.u;
    *(uint2*)(g_split_l + base + i0) = L.u;
}

// ================= pipelined wmma GEMM cores =================
// Split bf16: C += Ah@Bh^T + Ah@Bl^T + Al@Bh^T  (fp32 accum), K chunk 32, 2 stages.
typedef wmma::fragment<wmma::accumulator, 16, 16, 16, float> FragC;

// ---- rr: A [M,K] row-major (M tile 128), B [N,K] row-major (N tile NT) ----
template<int NT>
__device__ __forceinline__ void rr_load(
    const __nv_bfloat16* __restrict__ Ah, const __nv_bfloat16* __restrict__ Al, int lda, int m0,
    const __nv_bfloat16* __restrict__ Bh, const __nv_bfloat16* __restrict__ Bl, int ldb, int n0,
    int k0, uint32_t stage)
{
    const int tid = threadIdx.x;
#pragma unroll
    for (int rep = 0; rep < 2; rep++) {
        int idx = tid + rep * 256;             // 512 chunks: 128 rows x 4
        int r = idx >> 2, c8 = (idx & 3) * 8;
        uint32_t d = stage + (uint32_t)(r * 40 + c8) * 2;
        size_t off = (size_t)(m0 + r) * lda + k0 + c8;
        cp16(d, Ah + off);
        cp16(d + 10240, Al + off);
    }
#pragma unroll
    for (int rep = 0; rep < NT / 64; rep++) {
        int idx = tid + rep * 256;
        int r = idx >> 2, c8 = (idx & 3) * 8;
        uint32_t d = stage + 20480 + (uint32_t)(r * 40 + c8) * 2;
        size_t off = (size_t)(n0 + r) * ldb + k0 + c8;
        cp16(d, Bh + off);
        cp16(d + NT * 80, Bl + off);
    }
}

template<int NT>
__device__ __forceinline__ void rr_compute(const char* st, FragC (&c)[2][NT / 32])
{
    const int wid = threadIdx.x >> 5;
    const int wm0 = (wid >> 1) * 32;
    const int wn0 = (wid & 1) * (NT / 2);
    const __nv_bfloat16* sAh = (const __nv_bfloat16*)st;
    const __nv_bfloat16* sAl = sAh + 128 * 40;
    const __nv_bfloat16* sBh = (const __nv_bfloat16*)(st + 20480);
    const __nv_bfloat16* sBl = sBh + NT * 40;
    constexpr int FN = NT / 32;
#pragma unroll
    for (int kk = 0; kk < 32; kk += 16) {
        wmma::fragment<wmma::matrix_a, 16, 16, 16, __nv_bfloat16, wmma::row_major> aH[2], aL[2];
        wmma::fragment<wmma::matrix_b, 16, 16, 16, __nv_bfloat16, wmma::col_major> bH[FN], bL[FN];
#pragma unroll
        for (int i = 0; i < 2; i++) {
            wmma::load_matrix_sync(aH[i], sAh + (wm0 + 16 * i) * 40 + kk, 40);
            wmma::load_matrix_sync(aL[i], sAl + (wm0 + 16 * i) * 40 + kk, 40);
        }
#pragma unroll
        for (int j = 0; j < FN; j++) {
            wmma::load_matrix_sync(bH[j], sBh + (wn0 + 16 * j) * 40 + kk, 40);
            wmma::load_matrix_sync(bL[j], sBl + (wn0 + 16 * j) * 40 + kk, 40);
        }
#pragma unroll
        for (int i = 0; i < 2; i++)
#pragma unroll
            for (int j = 0; j < FN; j++) {
                wmma::mma_sync(c[i][j], aH[i], bH[j], c[i][j]);
                wmma::mma_sync(c[i][j], aH[i], bL[j], c[i][j]);
                wmma::mma_sync(c[i][j], aL[i], bH[j], c[i][j]);
            }
    }
}

template<int NT>
__device__ __forceinline__ void gemm_rr_pipe(
    const __nv_bfloat16* Ah, const __nv_bfloat16* Al, int lda, int m0,
    const __nv_bfloat16* Bh, const __nv_bfloat16* Bl, int ldb, int n0,
    int K, char* smem, FragC (&c)[2][NT / 32])
{
    const int SSTR = 20480 + NT * 160;
    uint32_t sb = smem_u32(smem);
#pragma unroll
    for (int i = 0; i < 2; i++)
#pragma unroll
        for (int j = 0; j < NT / 32; j++) wmma::fill_fragment(c[i][j], 0.f);
    rr_load<NT>(Ah, Al, lda, m0, Bh, Bl, ldb, n0, 0, sb);
    CP_COMMIT;
    const int NC = K / 32;
    for (int ch = 0; ch < NC; ch++) {
        if (ch + 1 < NC) {
            rr_load<NT>(Ah, Al, lda, m0, Bh, Bl, ldb, n0, (ch + 1) * 32,
                        sb + ((ch + 1) & 1) * SSTR);
            CP_COMMIT;
            asm volatile("cp.async.wait_group 1;" ::: "memory");
        } else {
            asm volatile("cp.async.wait_group 0;" ::: "memory");
        }
        __syncthreads();
        rr_compute<NT>(smem + (ch & 1) * SSTR, c);
        __syncthreads();
    }
}

// ---- kk: A [K,M] K-major (M tile 128), B [K,N] K-major (N tile 64) ----
__device__ __forceinline__ void kk_load(
    const __nv_bfloat16* __restrict__ Ah, const __nv_bfloat16* __restrict__ Al, int lda, int m0,
    const __nv_bfloat16* __restrict__ Bh, const __nv_bfloat16* __restrict__ Bl, int ldb, int n0,
    int k0, uint32_t stage)
{
    const int tid = threadIdx.x;
#pragma unroll
    for (int rep = 0; rep < 2; rep++) {
        int idx = tid + rep * 256;              // 512 chunks: 32 rows x 16
        int r = idx >> 4, c8 = (idx & 15) * 8;
        uint32_t d = stage + (uint32_t)(r * 136 + c8) * 2;
        size_t off = (size_t)(k0 + r) * lda + m0 + c8;
        cp16(d, Ah + off);
        cp16(d + 8704, Al + off);
    }
    {
        int r = tid >> 3, c8 = (tid & 7) * 8;   // 256 chunks: 32 rows x 8
        uint32_t d = stage + 17408 + (uint32_t)(r * 72 + c8) * 2;
        size_t off = (size_t)(k0 + r) * ldb + n0 + c8;
        cp16(d, Bh + off);
        cp16(d + 4608, Bl + off);
    }
}

__device__ __forceinline__ void kk_compute(const char* st, FragC (&c)[2][2])
{
    const int wid = threadIdx.x >> 5;
    const int wm0 = (wid >> 1) * 32;
    const int wn0 = (wid & 1) * 32;
    const __nv_bfloat16* sAh = (const __nv_bfloat16*)st;
    const __nv_bfloat16* sAl = sAh + 32 * 136;
    const __nv_bfloat16* sBh = (const __nv_bfloat16*)(st + 17408);
    const __nv_bfloat16* sBl = sBh + 32 * 72;
#pragma unroll
    for (int kk = 0; kk < 32; kk += 16) {
        wmma::fragment<wmma::matrix_a, 16, 16, 16, __nv_bfloat16, wmma::col_major> aH[2], aL[2];
        wmma::fragment<wmma::matrix_b, 16, 16, 16, __nv_bfloat16, wmma::row_major> bH[2], bL[2];
#pragma unroll
        for (int i = 0; i < 2; i++) {
            wmma::load_matrix_sync(aH[i], sAh + kk * 136 + wm0 + 16 * i, 136);
            wmma::load_matrix_sync(aL[i], sAl + kk * 136 + wm0 + 16 * i, 136);
        }
#pragma unroll
        for (int j = 0; j < 2; j++) {
            wmma::load_matrix_sync(bH[j], sBh + kk * 72 + wn0 + 16 * j, 72);
            wmma::load_matrix_sync(bL[j], sBl + kk * 72 + wn0 + 16 * j, 72);
        }
#pragma unroll
        for (int i = 0; i < 2; i++)
#pragma unroll
            for (int j = 0; j < 2; j++) {
                wmma::mma_sync(c[i][j], aH[i], bH[j], c[i][j]);
                wmma::mma_sync(c[i][j], aH[i], bL[j], c[i][j]);
                wmma::mma_sync(c[i][j], aL[i], bH[j], c[i][j]);
            }
    }
}

__device__ __forceinline__ void gemm_kk_pipe(
    const __nv_bfloat16* Ah, const __nv_bfloat16* Al, int lda, int m0,
    const __nv_bfloat16* Bh, const __nv_bfloat16* Bl, int ldb, int n0,
    int K, char* smem, FragC (&c)[2][2])
{
    const int SSTR = 26624;
    uint32_t sb = smem_u32(smem);
#pragma unroll
    for (int i = 0; i < 2; i++)
#pragma unroll
        for (int j = 0; j < 2; j++) wmma::fill_fragment(c[i][j], 0.f);
    kk_load(Ah, Al, lda, m0, Bh, Bl, ldb, n0, 0, sb);
    CP_COMMIT;
    const int NC = K / 32;
    for (int ch = 0; ch < NC; ch++) {
        if (ch + 1 < NC) {
            kk_load(Ah, Al, lda, m0, Bh, Bl, ldb, n0, (ch + 1) * 32,
                    sb + ((ch + 1) & 1) * SSTR);
            CP_COMMIT;
            asm volatile("cp.async.wait_group 1;" ::: "memory");
        } else {
            asm volatile("cp.async.wait_group 0;" ::: "memory");
        }
        __syncthreads();
        kk_compute(smem + (ch & 1) * SSTR, c);
        __syncthreads();
    }
}

// epilogue scratch overlay: per warp 32 x (WN+4) floats on top of pipeline smem
template<int WN, int FN>
__device__ __forceinline__ float* epi_store(FragC (&c)[2][FN], char* smem, int wid)
{
    float* sC = (float*)smem + wid * 32 * (WN + 4);
#pragma unroll
    for (int i = 0; i < 2; i++)
#pragma unroll
        for (int j = 0; j < FN; j++)
            wmma::store_matrix_sync(sC + i * 16 * (WN + 4) + j * 16, c[i][j],
                                    WN + 4, wmma::mem_row_major);
    __syncwarp();
    return sC;
}

// ---- qkv: proj_z[atom][hc] = in_z @ W_z^T + b_z, written as hi/lo bf16 ----
__global__ void __launch_bounds__(256, 2) qkv_wmma(
    const float* __restrict__ bq, const float* __restrict__ bk, const float* __restrict__ bv)
{
    extern __shared__ char smem[];
    const int tid = threadIdx.x, wid = tid >> 5, lane = tid & 31;
    const int z  = blockIdx.z;
    const int m0 = blockIdx.y * 128;   // atom
    const int n0 = blockIdx.x * 128;   // hc
    const float* bias = (z == 0) ? bq : (z == 1) ? bk : bv;
    FragC c[2][4];
    gemm_rr_pipe<128>(g_split_h + (size_t)z * SEG,       g_split_l + (size_t)z * SEG,       INC, m0,
                      g_split_h + (size_t)(3 + z) * SEG, g_split_l + (size_t)(3 + z) * SEG, INC, n0,
                      INC, smem, c);
    float* sC = epi_store<64, 4>(c, smem, wid);
    const int wm0 = (wid >> 1) * 32, wn0 = (wid & 1) * 64;
    const int atom = m0 + wm0 + lane;
    const size_t ob = (size_t)z * NA * HC + (size_t)atom * HC + n0 + wn0;
    union { __nv_bfloat16 b[8]; uint4 u; } H, L;
#pragma unroll
    for (int t = 0; t < 8; t++) {
#pragma unroll
        for (int e = 0; e < 8; e++) {
            float val = sC[lane * 68 + t * 8 + e] + bias[n0 + wn0 + t * 8 + e];
            split2(val, H.b[e], L.b[e]);
        }
        *(uint4*)(g_ph + ob + t * 8) = H.u;
        *(uint4*)(g_pl + ob + t * 8) = L.u;
    }
}

// ---- s0: ES0[h][a][n] = exp(dot(kp_a, qp_n)/sqrt(D)) ----
__global__ void __launch_bounds__(256, 2) s0_wmma()
{
    extern __shared__ char smem[];
    const int tid = threadIdx.x, wid = tid >> 5, lane = tid & 31;
    const int h  = blockIdx.z;
    const int m0 = blockIdx.y * 128;   // a
    const int n0 = blockIdx.x * 128;   // n
    FragC c[2][4];
    gemm_rr_pipe<128>(g_ph + 1 * NA * HC + h * HD, g_pl + 1 * NA * HC + h * HD, HC, m0,
                      g_ph + 0 * NA * HC + h * HD, g_pl + 0 * NA * HC + h * HD, HC, n0,
                      HD, smem, c);
    float* sC = epi_store<64, 4>(c, smem, wid);
    const int wm0 = (wid >> 1) * 32, wn0 = (wid & 1) * 64;
    const int a = m0 + wm0 + lane;
    const float scale = 0.08838834764831845f;   // 1/sqrt(128)
    float* dst = g_ES0 + ((size_t)h * NA + a) * NA + n0 + wn0;
#pragma unroll
    for (int t = 0; t < 16; t++) {
        float4 r;
        r.x = __expf(sC[lane * 68 + t * 4 + 0] * scale);
        r.y = __expf(sC[lane * 68 + t * 4 + 1] * scale);
        r.z = __expf(sC[lane * 68 + t * 4 + 2] * scale);
        r.w = __expf(sC[lane * 68 + t * 4 + 3] * scale);
        *(float4*)(dst + t * 4) = r;
    }
}

// ---- out2: attn[n][h*HD+d] = sum_a W2[h][a][n] * vp[a][h*HD+d] ----
__global__ void __launch_bounds__(256, 2) out2_wmma()
{
    extern __shared__ char smem[];
    const int tid = threadIdx.x, wid = tid >> 5, lane = tid & 31;
    const int h  = blockIdx.z;
    const int m0 = blockIdx.y * 128;   // n
    const int n0 = blockIdx.x * 64;    // d
    FragC c[2][2];
    gemm_kk_pipe(g_W2h + (size_t)h * NA * NA, g_W2l + (size_t)h * NA * NA, NA, m0,
                 g_ph + 2 * NA * HC + h * HD, g_pl + 2 * NA * HC + h * HD, HC, n0,
                 NA, smem, c);
    float* sC = epi_store<32, 2>(c, smem, wid);
    const int wm0 = (wid >> 1) * 32, wn0 = (wid & 1) * 32;
    const int n = m0 + wm0 + lane;
    float* dst = g_attn + (size_t)n * HC + h * HD + n0 + wn0;
#pragma unroll
    for (int t = 0; t < 8; t++) {
        float4 r;
        r.x = sC[lane * 36 + t * 4 + 0];
        r.y = sC[lane * 36 + t * 4 + 1];
        r.z = sC[lane * 36 + t * 4 + 2];
        r.w = sC[lane * 36 + t * 4 + 3];
        *(float4*)(dst + t * 4) = r;
    }
}

// ---- final: out[n][ic] = ln @ Wo^T + bo ----
__global__ void __launch_bounds__(256, 2) final_wmma(
    const float* __restrict__ bo, float* __restrict__ out)
{
    extern __shared__ char smem[];
    const int tid = threadIdx.x, wid = tid >> 5, lane = tid & 31;
    const int m0 = blockIdx.y * 128;   // n
    const int n0 = blockIdx.x * 128;   // ic
    FragC c[2][4];
    gemm_rr_pipe<128>(g_lnh, g_lnl, HC, m0,
                      g_split_h + 6 * SEG, g_split_l + 6 * SEG, HC, n0,
                      HC, smem, c);
    float* sC = epi_store<64, 4>(c, smem, wid);
    const int wm0 = (wid >> 1) * 32, wn0 = (wid & 1) * 64;
    const int n = m0 + wm0 + lane;
    float* dst = out + (size_t)n * INC + n0 + wn0;
#pragma unroll
    for (int t = 0; t < 16; t++) {
        float4 r;
        r.x = sC[lane * 68 + t * 4 + 0] + bo[n0 + wn0 + t * 4 + 0];
        r.y = sC[lane * 68 + t * 4 + 1] + bo[n0 + wn0 + t * 4 + 1];
        r.z = sC[lane * 68 + t * 4 + 2] + bo[n0 + wn0 + t * 4 + 2];
        r.w = sC[lane * 68 + t * 4 + 3] + bo[n0 + wn0 + t * 4 + 3];
        *(float4*)(dst + t * 4) = r;
    }
}

// ---------------- EB[m][n] = exp(attn_bias[n][m]) ----------------
__global__ void __launch_bounds__(256) transpose_exp(const float* __restrict__ src)
{
    __shared__ float tile[64][65];
    const int m0 = blockIdx.x * 64, n0 = blockIdx.y * 64;
    const int tid = threadIdx.x;
    const int r = tid >> 4, c4 = (tid & 15) * 4;
#pragma unroll
    for (int p = 0; p < 4; p++) {
        float4 vld = *(const float4*)(src + (size_t)(n0 + r + p * 16) * MM + m0 + c4);
        tile[r + p * 16][c4 + 0] = vld.x;
        tile[r + p * 16][c4 + 1] = vld.y;
        tile[r + p * 16][c4 + 2] = vld.z;
        tile[r + p * 16][c4 + 3] = vld.w;
    }
    __syncthreads();
#pragma unroll
    for (int p = 0; p < 4; p++) {
        const int mloc = r + p * 16;
        float4 o;
        o.x = __expf(tile[c4 + 0][mloc]);
        o.y = __expf(tile[c4 + 1][mloc]);
        o.z = __expf(tile[c4 + 2][mloc]);
        o.w = __expf(tile[c4 + 3][mloc]);
        *(float4*)(g_EB + (size_t)(m0 + mloc) * NA + n0 + c4) = o;
    }
}

// ---------------- seg (binary search) + CSR histogram/scan, fused, 1 CTA ------------
__global__ void __launch_bounds__(1024) seg_hist_kernel(
    const int* __restrict__ batch_index, const int* __restrict__ atom_index)
{
    __shared__ int buf[1024];
    const int tid = threadIdx.x;
    if (tid <= BB) {
        int lo = 0, hi = EE;
        while (lo < hi) {
            int mid = (lo + hi) >> 1;
            if (batch_index[mid] < tid) lo = mid + 1; else hi = mid;
        }
        g_seg[tid] = lo;
    }
    buf[tid] = 0;
    __syncthreads();
#pragma unroll
    for (int i = 0; i < EE / 1024; i++)
        atomicAdd(&buf[atom_index[tid + i * 1024]], 1);
    __syncthreads();
    for (int s = 1; s < 1024; s <<= 1) {
        int v = (tid >= s) ? buf[tid - s] : 0;
        __syncthreads();
        buf[tid] += v;
        __syncthreads();
    }
    g_off[tid + 1] = buf[tid];
    if (tid == 0) g_off[0] = 0;
}

__global__ void __launch_bounds__(256) fill_kernel(const int* __restrict__ atom_index)
{
    const int w = (blockIdx.x * 256 + threadIdx.x) >> 5;
    const int lane = threadIdx.x & 31;
    int o = g_off[w];
    for (int base = 0; base < EE; base += 32) {
        int a = atom_index[base + lane];
        bool match = (a == w);
        unsigned mask = __ballot_sync(0xffffffffu, match);
        int rank = __popc(mask & ((1u << lane) - 1));
        if (match) g_csr[o + rank] = base + lane;
        o += __popc(mask);
    }
}

// ---- C[b][h][n] = 1 / (sum_{e in b} env_e * EB[mp_e][n] * ES0[h][a_e][n] + 1e-16) ----
__global__ void __launch_bounds__(256) csum_kernel(
    const int* __restrict__ atom_index, const int* __restrict__ edge_map,
    const float* __restrict__ envelope)
{
    const int b = blockIdx.y;
    const int n = blockIdx.x * 256 + threadIdx.x;
    const int s0 = g_seg[b], s1 = g_seg[b + 1];
    __shared__ int   s_a[128], s_mp[128];
    __shared__ float s_env[128];
    float acc[NH] = {};
    for (int c = s0; c < s1; c += 128) {
        const int cnt = min(128, s1 - c);
        __syncthreads();
        if (threadIdx.x < cnt) {
            int e = c + threadIdx.x;
            int mp = edge_map[e];
            s_a[threadIdx.x]   = atom_index[e];
            s_mp[threadIdx.x]  = mp;
            s_env[threadIdx.x] = envelope[mp];
        }
        __syncthreads();
        for (int i = 0; i < cnt; i++) {
            float val = s_env[i] * g_EB[(size_t)s_mp[i] * NA + n];
            const float* es = g_ES0 + (size_t)s_a[i] * NA + n;
#pragma unroll
            for (int h = 0; h < NH; h++)
                acc[h] += val * es[(size_t)h * NA * NA];
        }
    }
#pragma unroll
    for (int h = 0; h < NH; h++)
        g_C[((size_t)b * NH + h) * NA + n] = 1.f / (acc[h] + 1e-16f);
}

// ---- W2[h][a][n] = ES0[h][a][n] * sum_{e->a} env_e^2 * EB[mp_e][n] * C[b_e][h][n] ----
__global__ void __launch_bounds__(128) w2_kernel(
    const int* __restrict__ edge_map, const int* __restrict__ batch_index,
    const float* __restrict__ envelope)
{
    const int a = blockIdx.y;
    const int n = blockIdx.x * 128 + threadIdx.x;
    const int o0 = g_off[a], o1 = g_off[a + 1];
    float acc[NH] = {};
    for (int j = o0; j < o1; j++) {
        int e  = g_csr[j];
        int mp = edge_map[e];
        int bb = batch_index[e];
        float env = envelope[mp];
        float t = env * env * g_EB[(size_t)mp * NA + n];
        const float* Cb = g_C + (size_t)bb * NH * NA + n;
#pragma unroll
        for (int h = 0; h < NH; h++)
            acc[h] += t * Cb[(size_t)h * NA];
    }
#pragma unroll
    for (int h = 0; h < NH; h++) {
        const size_t idx = ((size_t)h * NA + a) * NA + n;
        float val = g_ES0[idx] * acc[h];
        split2(val, g_W2h[idx], g_W2l[idx]);
    }
}

// ---------------- LayerNorm -> hi/lo bf16 ----------------
__global__ void __launch_bounds__(256) ln_kernel(
    const float* __restrict__ ln_g, const float* __restrict__ ln_b)
{
    const int n = blockIdx.x;
    const int tid = threadIdx.x;
    const float* x = g_attn + (size_t)n * HC;
    float s = 0.f, s2 = 0.f;
    for (int i = tid; i < HC; i += 256) {
        float v = x[i];
        s += v; s2 += v * v;
    }
#pragma unroll
    for (int o = 16; o > 0; o >>= 1) {
        s  += __shfl_xor_sync(0xffffffffu, s, o);
        s2 += __shfl_xor_sync(0xffffffffu, s2, o);
    }
    __shared__ float ws[8], ws2[8], stats[2];
    if ((tid & 31) == 0) { ws[tid >> 5] = s; ws2[tid >> 5] = s2; }
    __syncthreads();
    if (tid == 0) {
        float a = 0.f, b = 0.f;
#pragma unroll
        for (int i = 0; i < 8; i++) { a += ws[i]; b += ws2[i]; }
        float mean = a * (1.f / HC);
        float var  = b * (1.f / HC) - mean * mean;
        stats[0] = mean;
        stats[1] = rsqrtf(var + 1e-7f);
    }
    __syncthreads();
    const float mean = stats[0], inv = stats[1];
    for (int i = tid; i < HC; i += 256) {
        float val = (x[i] - mean) * inv * ln_g[i] + ln_b[i];
        split2(val, g_lnh[(size_t)n * HC + i], g_lnl[(size_t)n * HC + i]);
    }
}

// ---------------- launch ----------------
extern "C" void kernel_launch(void* const* d_in, const int* in_sizes, int n_in,
                              void* d_out, int out_size)
{
    const float* q         = (const float*)d_in[0];
    const float* k         = (const float*)d_in[1];
    const float* v         = (const float*)d_in[2];
    const float* envelope  = (const float*)d_in[3];
    const float* attn_bias = (const float*)d_in[4];
    const float* Wq        = (const float*)d_in[5];
    const float* bq        = (const float*)d_in[6];
    const float* Wk        = (const float*)d_in[7];
    const float* bk        = (const float*)d_in[8];
    const float* Wv        = (const float*)d_in[9];
    const float* bv        = (const float*)d_in[10];
    const float* ln_g      = (const float*)d_in[11];
    const float* ln_b      = (const float*)d_in[12];
    const float* Wo        = (const float*)d_in[13];
    const float* bo        = (const float*)d_in[14];
    const int* atom_index  = (const int*)d_in[15];
    const int* batch_index = (const int*)d_in[16];
    const int* edge_map    = (const int*)d_in[17];
    float* out = (float*)d_out;

    const int SMEM_RR = 2 * (20480 + 128 * 160);   // 81920
    const int SMEM_KK = 2 * 26624;                 // 53248
    cudaFuncSetAttribute(qkv_wmma,   cudaFuncAttributeMaxDynamicSharedMemorySize, SMEM_RR);
    cudaFuncSetAttribute(s0_wmma,    cudaFuncAttributeMaxDynamicSharedMemorySize, SMEM_RR);
    cudaFuncSetAttribute(final_wmma, cudaFuncAttributeMaxDynamicSharedMemorySize, SMEM_RR);
    cudaFuncSetAttribute(out2_wmma,  cudaFuncAttributeMaxDynamicSharedMemorySize, SMEM_KK);

    // 1. split all external GEMM operands into hi/lo bf16
    split_kernel<<<dim3(SEG / 1024, 7), 256>>>(q, k, v, Wq, Wk, Wv, Wo);

    // 2. projections (tensor cores, split-bf16)
    qkv_wmma<<<dim3(HC / 128, NA / 128, 3), 256, SMEM_RR>>>(bq, bk, bv);

    // 3. EB = exp(attn_bias^T)
    transpose_exp<<<dim3(MM / 64, NA / 64), 256>>>(attn_bias);

    // 4. dense per-atom exp(scores)  [profiled launch]
    s0_wmma<<<dim3(NA / 128, NA / 128, NH), 256, SMEM_RR>>>();

    // 5-6. segment boundaries + CSR
    seg_hist_kernel<<<1, 1024>>>(batch_index, atom_index);
    fill_kernel<<<NA / 8, 256>>>(atom_index);

    // 7-8. softmax denominators + per-atom weights
    csum_kernel<<<dim3(NA / 256, BB), 256>>>(atom_index, edge_map, envelope);
    w2_kernel<<<dim3(NA / 128, NA), 128>>>(edge_map, batch_index, envelope);

    // 9. attention output (tensor cores)
    out2_wmma<<<dim3(HD / 64, NA / 128, NH), 256, SMEM_KK>>>();

    // 10. layernorm
    ln_kernel<<<NA, 256>>>(ln_g, ln_b);

    // 11. final projection (tensor cores)
    final_wmma<<<dim3(INC / 128, NA / 128), 256, SMEM_RR>>>(bo, out);
}

// round 15
// speedup vs baseline: 1.2443x; 1.1379x over previous
#include <cuda_runtime.h>
#include <cuda_bf16.h>
#include <mma.h>
#include <cstdint>
#include <math.h>

using namespace nvcuda;

// Problem constants
#define NA  1024   // N atoms
#define EE  8192   // E edges
#define MM  8192   // M envelope table
#define BB  64     // B batches
#define INC 512    // IN_CH
#define HC  1024   // H_CH
#define NH  8      // heads
#define HD  128    // head dim

#define SEG 524288 // elements per split slab (all 7 external operands are 512K elems)

// ---------------- scratch ----------------
__device__ __nv_bfloat16 g_split_h[7 * SEG];     // q,k,v,Wq,Wk,Wv,Wo (hi)
__device__ __nv_bfloat16 g_split_l[7 * SEG];     // (lo)
__device__ __nv_bfloat16 g_ph[3 * NA * HC];      // qp/kp/vp hi
__device__ __nv_bfloat16 g_pl[3 * NA * HC];      // qp/kp/vp lo
__device__ __nv_bfloat16 g_lnh[NA * HC];
__device__ __nv_bfloat16 g_lnl[NA * HC];
__device__ __nv_bfloat16 g_W2h[(size_t)NH * NA * NA];
__device__ __nv_bfloat16 g_W2l[(size_t)NH * NA * NA];
__device__ float g_EB[(size_t)MM * NA];          // exp(attn_bias^T)[m][n]
__device__ float g_ES0[(size_t)NH * NA * NA];    // exp(S0)[h][a][n]
__device__ float g_C[BB * NH * NA];
__device__ float g_attn[NA * HC];                // out2 partial (a in [0,512))
__device__ float g_attn2[NA * HC];               // out2 partial (a in [512,1024))
__device__ float g_fpart[2 * NA * INC];          // final partials
__device__ int   g_seg[BB + 1];
__device__ int   g_off[NA + 1];
__device__ int   g_csr[EE];

__device__ __forceinline__ void split2(float v, __nv_bfloat16& h, __nv_bfloat16& l) {
    h = __float2bfloat16(v);
    l = __float2bfloat16(v - __bfloat162float(h));
}

__device__ __forceinline__ uint32_t smem_u32(const void* p) {
    return (uint32_t)__cvta_generic_to_shared(p);
}
__device__ __forceinline__ void cp16(uint32_t dst, const void* src) {
    asm volatile("cp.async.cg.shared.global [%0], [%1], 16;" :: "r"(dst), "l"(src));
}
#define CP_COMMIT asm volatile("cp.async.commit_group;" ::: "memory")

// ---------------- split the 7 external fp32 operands into hi/lo bf16 ----------------
__global__ void __launch_bounds__(256) split_kernel(
    const float* __restrict__ q,  const float* __restrict__ k,  const float* __restrict__ v,
    const float* __restrict__ Wq, const float* __restrict__ Wk, const float* __restrict__ Wv,
    const float* __restrict__ Wo)
{
    const float* srcs[7] = {q, k, v, Wq, Wk, Wv, Wo};
    const float* s = srcs[blockIdx.y];
    const size_t base = (size_t)blockIdx.y * SEG;
    const int i0 = (blockIdx.x * 256 + threadIdx.x) * 4;
    float4 f = *(const float4*)(s + i0);
    union { __nv_bfloat16 b[4]; uint2 u; } H, L;
    split2(f.x, H.b[0], L.b[0]);
    split2(f.y, H.b[1], L.b[1]);
    split2(f.z, H.b[2], L.b[2]);
    split2(f.w, H.b[3], L.b[3]);
    *(uint2*)(g_split_h + base + i0) = H.u;
    *(uint2*)(g_split_l + base + i0) = L.u;
}

// ================= pipelined wmma GEMM cores =================
// Split bf16: C += Ah@Bh^T + Ah@Bl^T + Al@Bh^T  (fp32 accum), K chunk 32, 2 stages.
typedef wmma::fragment<wmma::accumulator, 16, 16, 16, float> FragC;

// ---- rr: A [M,K] row-major (M tile 128), B [N,K] row-major (N tile NT) ----
template<int NT>
__device__ __forceinline__ void rr_load(
    const __nv_bfloat16* __restrict__ Ah, const __nv_bfloat16* __restrict__ Al, int lda, int m0,
    const __nv_bfloat16* __restrict__ Bh, const __nv_bfloat16* __restrict__ Bl, int ldb, int n0,
    int k0, uint32_t stage)
{
    const int tid = threadIdx.x;
#pragma unroll
    for (int rep = 0; rep < 2; rep++) {
        int idx = tid + rep * 256;             // 512 chunks: 128 rows x 4
        int r = idx >> 2, c8 = (idx & 3) * 8;
        uint32_t d = stage + (uint32_t)(r * 40 + c8) * 2;
        size_t off = (size_t)(m0 + r) * lda + k0 + c8;
        cp16(d, Ah + off);
        cp16(d + 10240, Al + off);
    }
#pragma unroll
    for (int rep = 0; rep < NT / 64; rep++) {
        int idx = tid + rep * 256;
        int r = idx >> 2, c8 = (idx & 3) * 8;
        uint32_t d = stage + 20480 + (uint32_t)(r * 40 + c8) * 2;
        size_t off = (size_t)(n0 + r) * ldb + k0 + c8;
        cp16(d, Bh + off);
        cp16(d + NT * 80, Bl + off);
    }
}

template<int NT>
__device__ __forceinline__ void rr_compute(const char* st, FragC (&c)[2][NT / 32])
{
    const int wid = threadIdx.x >> 5;
    const int wm0 = (wid >> 1) * 32;
    const int wn0 = (wid & 1) * (NT / 2);
    const __nv_bfloat16* sAh = (const __nv_bfloat16*)st;
    const __nv_bfloat16* sAl = sAh + 128 * 40;
    const __nv_bfloat16* sBh = (const __nv_bfloat16*)(st + 20480);
    const __nv_bfloat16* sBl = sBh + NT * 40;
    constexpr int FN = NT / 32;
#pragma unroll
    for (int kk = 0; kk < 32; kk += 16) {
        wmma::fragment<wmma::matrix_a, 16, 16, 16, __nv_bfloat16, wmma::row_major> aH[2], aL[2];
        wmma::fragment<wmma::matrix_b, 16, 16, 16, __nv_bfloat16, wmma::col_major> bH[FN], bL[FN];
#pragma unroll
        for (int i = 0; i < 2; i++) {
            wmma::load_matrix_sync(aH[i], sAh + (wm0 + 16 * i) * 40 + kk, 40);
            wmma::load_matrix_sync(aL[i], sAl + (wm0 + 16 * i) * 40 + kk, 40);
        }
#pragma unroll
        for (int j = 0; j < FN; j++) {
            wmma::load_matrix_sync(bH[j], sBh + (wn0 + 16 * j) * 40 + kk, 40);
            wmma::load_matrix_sync(bL[j], sBl + (wn0 + 16 * j) * 40 + kk, 40);
        }
#pragma unroll
        for (int i = 0; i < 2; i++)
#pragma unroll
            for (int j = 0; j < FN; j++) {
                wmma::mma_sync(c[i][j], aH[i], bH[j], c[i][j]);
                wmma::mma_sync(c[i][j], aH[i], bL[j], c[i][j]);
                wmma::mma_sync(c[i][j], aL[i], bH[j], c[i][j]);
            }
    }
}

template<int NT>
__device__ __forceinline__ void gemm_rr_pipe(
    const __nv_bfloat16* Ah, const __nv_bfloat16* Al, int lda, int m0,
    const __nv_bfloat16* Bh, const __nv_bfloat16* Bl, int ldb, int n0,
    int K, char* smem, FragC (&c)[2][NT / 32])
{
    const int SSTR = 20480 + NT * 160;
    uint32_t sb = smem_u32(smem);
#pragma unroll
    for (int i = 0; i < 2; i++)
#pragma unroll
        for (int j = 0; j < NT / 32; j++) wmma::fill_fragment(c[i][j], 0.f);
    rr_load<NT>(Ah, Al, lda, m0, Bh, Bl, ldb, n0, 0, sb);
    CP_COMMIT;
    const int NC = K / 32;
    for (int ch = 0; ch < NC; ch++) {
        if (ch + 1 < NC) {
            rr_load<NT>(Ah, Al, lda, m0, Bh, Bl, ldb, n0, (ch + 1) * 32,
                        sb + ((ch + 1) & 1) * SSTR);
            CP_COMMIT;
            asm volatile("cp.async.wait_group 1;" ::: "memory");
        } else {
            asm volatile("cp.async.wait_group 0;" ::: "memory");
        }
        __syncthreads();
        rr_compute<NT>(smem + (ch & 1) * SSTR, c);
        __syncthreads();
    }
}

// ---- kk: A [K,M] K-major (M tile 128), B [K,N] K-major (N tile 64) ----
__device__ __forceinline__ void kk_load(
    const __nv_bfloat16* __restrict__ Ah, const __nv_bfloat16* __restrict__ Al, int lda, int m0,
    const __nv_bfloat16* __restrict__ Bh, const __nv_bfloat16* __restrict__ Bl, int ldb, int n0,
    int k0, uint32_t stage)
{
    const int tid = threadIdx.x;
#pragma unroll
    for (int rep = 0; rep < 2; rep++) {
        int idx = tid + rep * 256;              // 512 chunks: 32 rows x 16
        int r = idx >> 4, c8 = (idx & 15) * 8;
        uint32_t d = stage + (uint32_t)(r * 136 + c8) * 2;
        size_t off = (size_t)(k0 + r) * lda + m0 + c8;
        cp16(d, Ah + off);
        cp16(d + 8704, Al + off);
    }
    {
        int r = tid >> 3, c8 = (tid & 7) * 8;   // 256 chunks: 32 rows x 8
        uint32_t d = stage + 17408 + (uint32_t)(r * 72 + c8) * 2;
        size_t off = (size_t)(k0 + r) * ldb + n0 + c8;
        cp16(d, Bh + off);
        cp16(d + 4608, Bl + off);
    }
}

__device__ __forceinline__ void kk_compute(const char* st, FragC (&c)[2][2])
{
    const int wid = threadIdx.x >> 5;
    const int wm0 = (wid >> 1) * 32;
    const int wn0 = (wid & 1) * 32;
    const __nv_bfloat16* sAh = (const __nv_bfloat16*)st;
    const __nv_bfloat16* sAl = sAh + 32 * 136;
    const __nv_bfloat16* sBh = (const __nv_bfloat16*)(st + 17408);
    const __nv_bfloat16* sBl = sBh + 32 * 72;
#pragma unroll
    for (int kk = 0; kk < 32; kk += 16) {
        wmma::fragment<wmma::matrix_a, 16, 16, 16, __nv_bfloat16, wmma::col_major> aH[2], aL[2];
        wmma::fragment<wmma::matrix_b, 16, 16, 16, __nv_bfloat16, wmma::row_major> bH[2], bL[2];
#pragma unroll
        for (int i = 0; i < 2; i++) {
            wmma::load_matrix_sync(aH[i], sAh + kk * 136 + wm0 + 16 * i, 136);
            wmma::load_matrix_sync(aL[i], sAl + kk * 136 + wm0 + 16 * i, 136);
        }
#pragma unroll
        for (int j = 0; j < 2; j++) {
            wmma::load_matrix_sync(bH[j], sBh + kk * 72 + wn0 + 16 * j, 72);
            wmma::load_matrix_sync(bL[j], sBl + kk * 72 + wn0 + 16 * j, 72);
        }
#pragma unroll
        for (int i = 0; i < 2; i++)
#pragma unroll
            for (int j = 0; j < 2; j++) {
                wmma::mma_sync(c[i][j], aH[i], bH[j], c[i][j]);
                wmma::mma_sync(c[i][j], aH[i], bL[j], c[i][j]);
                wmma::mma_sync(c[i][j], aL[i], bH[j], c[i][j]);
            }
    }
}

__device__ __forceinline__ void gemm_kk_pipe(
    const __nv_bfloat16* Ah, const __nv_bfloat16* Al, int lda, int m0,
    const __nv_bfloat16* Bh, const __nv_bfloat16* Bl, int ldb, int n0,
    int K, char* smem, FragC (&c)[2][2])
{
    const int SSTR = 26624;
    uint32_t sb = smem_u32(smem);
#pragma unroll
    for (int i = 0; i < 2; i++)
#pragma unroll
        for (int j = 0; j < 2; j++) wmma::fill_fragment(c[i][j], 0.f);
    kk_load(Ah, Al, lda, m0, Bh, Bl, ldb, n0, 0, sb);
    CP_COMMIT;
    const int NC = K / 32;
    for (int ch = 0; ch < NC; ch++) {
        if (ch + 1 < NC) {
            kk_load(Ah, Al, lda, m0, Bh, Bl, ldb, n0, (ch + 1) * 32,
                    sb + ((ch + 1) & 1) * SSTR);
            CP_COMMIT;
            asm volatile("cp.async.wait_group 1;" ::: "memory");
        } else {
            asm volatile("cp.async.wait_group 0;" ::: "memory");
        }
        __syncthreads();
        kk_compute(smem + (ch & 1) * SSTR, c);
        __syncthreads();
    }
}

// epilogue scratch overlay: per warp 32 x (WN+4) floats on top of pipeline smem
template<int WN, int FN>
__device__ __forceinline__ float* epi_store(FragC (&c)[2][FN], char* smem, int wid)
{
    float* sC = (float*)smem + wid * 32 * (WN + 4);
#pragma unroll
    for (int i = 0; i < 2; i++)
#pragma unroll
        for (int j = 0; j < FN; j++)
            wmma::store_matrix_sync(sC + i * 16 * (WN + 4) + j * 16, c[i][j],
                                    WN + 4, wmma::mem_row_major);
    __syncwarp();
    return sC;
}

// ---- qkv (NT=64): proj_z[atom][hc] = in_z @ W_z^T + b_z, written as hi/lo bf16 ----
__global__ void __launch_bounds__(256, 2) qkv_wmma(
    const float* __restrict__ bq, const float* __restrict__ bk, const float* __restrict__ bv)
{
    extern __shared__ char smem[];
    const int tid = threadIdx.x, wid = tid >> 5, lane = tid & 31;
    const int z  = blockIdx.z;
    const int m0 = blockIdx.y * 128;   // atom
    const int n0 = blockIdx.x * 64;    // hc
    const float* bias = (z == 0) ? bq : (z == 1) ? bk : bv;
    FragC c[2][2];
    gemm_rr_pipe<64>(g_split_h + (size_t)z * SEG,       g_split_l + (size_t)z * SEG,       INC, m0,
                     g_split_h + (size_t)(3 + z) * SEG, g_split_l + (size_t)(3 + z) * SEG, INC, n0,
                     INC, smem, c);
    float* sC = epi_store<32, 2>(c, smem, wid);
    const int wm0 = (wid >> 1) * 32, wn0 = (wid & 1) * 32;
    const int atom = m0 + wm0 + lane;
    const size_t ob = (size_t)z * NA * HC + (size_t)atom * HC + n0 + wn0;
    union { __nv_bfloat16 b[8]; uint4 u; } H, L;
#pragma unroll
    for (int t = 0; t < 4; t++) {
#pragma unroll
        for (int e = 0; e < 8; e++) {
            float val = sC[lane * 36 + t * 8 + e] + bias[n0 + wn0 + t * 8 + e];
            split2(val, H.b[e], L.b[e]);
        }
        *(uint4*)(g_ph + ob + t * 8) = H.u;
        *(uint4*)(g_pl + ob + t * 8) = L.u;
    }
}

// ---- s0 (NT=128, control): ES0[h][a][n] = exp(dot(kp_a, qp_n)/sqrt(D)) ----
__global__ void __launch_bounds__(256, 2) s0_wmma()
{
    extern __shared__ char smem[];
    const int tid = threadIdx.x, wid = tid >> 5, lane = tid & 31;
    const int h  = blockIdx.z;
    const int m0 = blockIdx.y * 128;   // a
    const int n0 = blockIdx.x * 128;   // n
    FragC c[2][4];
    gemm_rr_pipe<128>(g_ph + 1 * NA * HC + h * HD, g_pl + 1 * NA * HC + h * HD, HC, m0,
                      g_ph + 0 * NA * HC + h * HD, g_pl + 0 * NA * HC + h * HD, HC, n0,
                      HD, smem, c);
    float* sC = epi_store<64, 4>(c, smem, wid);
    const int wm0 = (wid >> 1) * 32, wn0 = (wid & 1) * 64;
    const int a = m0 + wm0 + lane;
    const float scale = 0.08838834764831845f;   // 1/sqrt(128)
    float* dst = g_ES0 + ((size_t)h * NA + a) * NA + n0 + wn0;
#pragma unroll
    for (int t = 0; t < 16; t++) {
        float4 r;
        r.x = __expf(sC[lane * 68 + t * 4 + 0] * scale);
        r.y = __expf(sC[lane * 68 + t * 4 + 1] * scale);
        r.z = __expf(sC[lane * 68 + t * 4 + 2] * scale);
        r.w = __expf(sC[lane * 68 + t * 4 + 3] * scale);
        *(float4*)(dst + t * 4) = r;
    }
}

// ---- out2 (K-split x2): partial[n][h*HD+d] = sum_{a in half} W2[h][a][n]*vp[a][h*HD+d]
__global__ void __launch_bounds__(256, 2) out2_wmma()
{
    extern __shared__ char smem[];
    const int tid = threadIdx.x, wid = tid >> 5, lane = tid & 31;
    const int h    = blockIdx.z & 7;
    const int half = blockIdx.z >> 3;
    const int m0 = blockIdx.y * 128;   // n
    const int n0 = blockIdx.x * 64;    // d
    const size_t koff = (size_t)half * 512;
    FragC c[2][2];
    gemm_kk_pipe(g_W2h + (size_t)h * NA * NA + koff * NA,
                 g_W2l + (size_t)h * NA * NA + koff * NA, NA, m0,
                 g_ph + 2 * NA * HC + h * HD + koff * HC,
                 g_pl + 2 * NA * HC + h * HD + koff * HC, HC, n0,
                 512, smem, c);
    float* sC = epi_store<32, 2>(c, smem, wid);
    const int wm0 = (wid >> 1) * 32, wn0 = (wid & 1) * 32;
    const int n = m0 + wm0 + lane;
    float* base = half ? g_attn2 : g_attn;
    float* dst = base + (size_t)n * HC + h * HD + n0 + wn0;
#pragma unroll
    for (int t = 0; t < 8; t++) {
        float4 r;
        r.x = sC[lane * 36 + t * 4 + 0];
        r.y = sC[lane * 36 + t * 4 + 1];
        r.z = sC[lane * 36 + t * 4 + 2];
        r.w = sC[lane * 36 + t * 4 + 3];
        *(float4*)(dst + t * 4) = r;
    }
}

// ---- final (NT=64, K-split x2): partial = ln @ Wo^T over half of HC ----
__global__ void __launch_bounds__(256, 2) final_wmma()
{
    extern __shared__ char smem[];
    const int tid = threadIdx.x, wid = tid >> 5, lane = tid & 31;
    const int half = blockIdx.z;
    const int m0 = blockIdx.y * 128;   // n
    const int n0 = blockIdx.x * 64;    // ic
    const int koff = half * 512;
    FragC c[2][2];
    gemm_rr_pipe<64>(g_lnh + koff, g_lnl + koff, HC, m0,
                     g_split_h + 6 * SEG + koff, g_split_l + 6 * SEG + koff, HC, n0,
                     512, smem, c);
    float* sC = epi_store<32, 2>(c, smem, wid);
    const int wm0 = (wid >> 1) * 32, wn0 = (wid & 1) * 32;
    const int n = m0 + wm0 + lane;
    float* dst = g_fpart + (size_t)half * NA * INC + (size_t)n * INC + n0 + wn0;
#pragma unroll
    for (int t = 0; t < 8; t++) {
        float4 r;
        r.x = sC[lane * 36 + t * 4 + 0];
        r.y = sC[lane * 36 + t * 4 + 1];
        r.z = sC[lane * 36 + t * 4 + 2];
        r.w = sC[lane * 36 + t * 4 + 3];
        *(float4*)(dst + t * 4) = r;
    }
}

// ---- final combine: out = p0 + p1 + bo ----
__global__ void __launch_bounds__(256) final_combine(
    const float* __restrict__ bo, float* __restrict__ out)
{
    const int i4 = (blockIdx.x * 256 + threadIdx.x) * 4;
    float4 a = *(const float4*)(g_fpart + i4);
    float4 b = *(const float4*)(g_fpart + NA * INC + i4);
    float4 bb = *(const float4*)(bo + (i4 & (INC - 1)));
    float4 r;
    r.x = a.x + b.x + bb.x;
    r.y = a.y + b.y + bb.y;
    r.z = a.z + b.z + bb.z;
    r.w = a.w + b.w + bb.w;
    *(float4*)(out + i4) = r;
}

// ---------------- EB[m][n] = exp(attn_bias[n][m]) ----------------
__global__ void __launch_bounds__(256) transpose_exp(const float* __restrict__ src)
{
    __shared__ float tile[64][65];
    const int m0 = blockIdx.x * 64, n0 = blockIdx.y * 64;
    const int tid = threadIdx.x;
    const int r = tid >> 4, c4 = (tid & 15) * 4;
#pragma unroll
    for (int p = 0; p < 4; p++) {
        float4 vld = *(const float4*)(src + (size_t)(n0 + r + p * 16) * MM + m0 + c4);
        tile[r + p * 16][c4 + 0] = vld.x;
        tile[r + p * 16][c4 + 1] = vld.y;
        tile[r + p * 16][c4 + 2] = vld.z;
        tile[r + p * 16][c4 + 3] = vld.w;
    }
    __syncthreads();
#pragma unroll
    for (int p = 0; p < 4; p++) {
        const int mloc = r + p * 16;
        float4 o;
        o.x = __expf(tile[c4 + 0][mloc]);
        o.y = __expf(tile[c4 + 1][mloc]);
        o.z = __expf(tile[c4 + 2][mloc]);
        o.w = __expf(tile[c4 + 3][mloc]);
        *(float4*)(g_EB + (size_t)(m0 + mloc) * NA + n0 + c4) = o;
    }
}

// ---------------- seg (binary search) + CSR histogram/scan, fused, 1 CTA ------------
__global__ void __launch_bounds__(1024) seg_hist_kernel(
    const int* __restrict__ batch_index, const int* __restrict__ atom_index)
{
    __shared__ int buf[1024];
    const int tid = threadIdx.x;
    if (tid <= BB) {
        int lo = 0, hi = EE;
        while (lo < hi) {
            int mid = (lo + hi) >> 1;
            if (batch_index[mid] < tid) lo = mid + 1; else hi = mid;
        }
        g_seg[tid] = lo;
    }
    buf[tid] = 0;
    __syncthreads();
#pragma unroll
    for (int i = 0; i < EE / 1024; i++)
        atomicAdd(&buf[atom_index[tid + i * 1024]], 1);
    __syncthreads();
    for (int s = 1; s < 1024; s <<= 1) {
        int v = (tid >= s) ? buf[tid - s] : 0;
        __syncthreads();
        buf[tid] += v;
        __syncthreads();
    }
    g_off[tid + 1] = buf[tid];
    if (tid == 0) g_off[0] = 0;
}

__global__ void __launch_bounds__(256) fill_kernel(const int* __restrict__ atom_index)
{
    const int w = (blockIdx.x * 256 + threadIdx.x) >> 5;
    const int lane = threadIdx.x & 31;
    int o = g_off[w];
    for (int base = 0; base < EE; base += 32) {
        int a = atom_index[base + lane];
        bool match = (a == w);
        unsigned mask = __ballot_sync(0xffffffffu, match);
        int rank = __popc(mask & ((1u << lane) - 1));
        if (match) g_csr[o + rank] = base + lane;
        o += __popc(mask);
    }
}

// ---- C[b][h][n] = 1 / (sum_{e in b} env_e * EB[mp_e][n] * ES0[h][a_e][n] + 1e-16) ----
__global__ void __launch_bounds__(256) csum_kernel(
    const int* __restrict__ atom_index, const int* __restrict__ edge_map,
    const float* __restrict__ envelope)
{
    const int b = blockIdx.y;
    const int n = blockIdx.x * 256 + threadIdx.x;
    const int s0 = g_seg[b], s1 = g_seg[b + 1];
    __shared__ int   s_a[128], s_mp[128];
    __shared__ float s_env[128];
    float acc[NH] = {};
    for (int c = s0; c < s1; c += 128) {
        const int cnt = min(128, s1 - c);
        __syncthreads();
        if (threadIdx.x < cnt) {
            int e = c + threadIdx.x;
            int mp = edge_map[e];
            s_a[threadIdx.x]   = atom_index[e];
            s_mp[threadIdx.x]  = mp;
            s_env[threadIdx.x] = envelope[mp];
        }
        __syncthreads();
        for (int i = 0; i < cnt; i++) {
            float val = s_env[i] * g_EB[(size_t)s_mp[i] * NA + n];
            const float* es = g_ES0 + (size_t)s_a[i] * NA + n;
#pragma unroll
            for (int h = 0; h < NH; h++)
                acc[h] += val * es[(size_t)h * NA * NA];
        }
    }
#pragma unroll
    for (int h = 0; h < NH; h++)
        g_C[((size_t)b * NH + h) * NA + n] = 1.f / (acc[h] + 1e-16f);
}

// ---- W2[h][a][n] = ES0[h][a][n] * sum_{e->a} env_e^2 * EB[mp_e][n] * C[b_e][h][n] ----
__global__ void __launch_bounds__(128) w2_kernel(
    const int* __restrict__ edge_map, const int* __restrict__ batch_index,
    const float* __restrict__ envelope)
{
    const int a = blockIdx.y;
    const int n = blockIdx.x * 128 + threadIdx.x;
    const int o0 = g_off[a], o1 = g_off[a + 1];
    float acc[NH] = {};
    for (int j = o0; j < o1; j++) {
        int e  = g_csr[j];
        int mp = edge_map[e];
        int bb = batch_index[e];
        float env = envelope[mp];
        float t = env * env * g_EB[(size_t)mp * NA + n];
        const float* Cb = g_C + (size_t)bb * NH * NA + n;
#pragma unroll
        for (int h = 0; h < NH; h++)
            acc[h] += t * Cb[(size_t)h * NA];
    }
#pragma unroll
    for (int h = 0; h < NH; h++) {
        const size_t idx = ((size_t)h * NA + a) * NA + n;
        float val = g_ES0[idx] * acc[h];
        split2(val, g_W2h[idx], g_W2l[idx]);
    }
}

// ---------------- LayerNorm (sums the two out2 partials) -> hi/lo bf16 ----------------
__global__ void __launch_bounds__(256) ln_kernel(
    const float* __restrict__ ln_g, const float* __restrict__ ln_b)
{
    const int n = blockIdx.x;
    const int tid = threadIdx.x;
    const float* x0 = g_attn  + (size_t)n * HC;
    const float* x1 = g_attn2 + (size_t)n * HC;
    float s = 0.f, s2 = 0.f;
    for (int i = tid; i < HC; i += 256) {
        float v = x0[i] + x1[i];
        s += v; s2 += v * v;
    }
#pragma unroll
    for (int o = 16; o > 0; o >>= 1) {
        s  += __shfl_xor_sync(0xffffffffu, s, o);
        s2 += __shfl_xor_sync(0xffffffffu, s2, o);
    }
    __shared__ float ws[8], ws2[8], stats[2];
    if ((tid & 31) == 0) { ws[tid >> 5] = s; ws2[tid >> 5] = s2; }
    __syncthreads();
    if (tid == 0) {
        float a = 0.f, b = 0.f;
#pragma unroll
        for (int i = 0; i < 8; i++) { a += ws[i]; b += ws2[i]; }
        float mean = a * (1.f / HC);
        float var  = b * (1.f / HC) - mean * mean;
        stats[0] = mean;
        stats[1] = rsqrtf(var + 1e-7f);
    }
    __syncthreads();
    const float mean = stats[0], inv = stats[1];
    for (int i = tid; i < HC; i += 256) {
        float val = (x0[i] + x1[i] - mean) * inv * ln_g[i] + ln_b[i];
        split2(val, g_lnh[(size_t)n * HC + i], g_lnl[(size_t)n * HC + i]);
    }
}

// ---------------- launch ----------------
extern "C" void kernel_launch(void* const* d_in, const int* in_sizes, int n_in,
                              void* d_out, int out_size)
{
    const float* q         = (const float*)d_in[0];
    const float* k         = (const float*)d_in[1];
    const float* v         = (const float*)d_in[2];
    const float* envelope  = (const float*)d_in[3];
    const float* attn_bias = (const float*)d_in[4];
    const float* Wq        = (const float*)d_in[5];
    const float* bq        = (const float*)d_in[6];
    const float* Wk        = (const float*)d_in[7];
    const float* bk        = (const float*)d_in[8];
    const float* Wv        = (const float*)d_in[9];
    const float* bv        = (const float*)d_in[10];
    const float* ln_g      = (const float*)d_in[11];
    const float* ln_b      = (const float*)d_in[12];
    const float* Wo        = (const float*)d_in[13];
    const float* bo        = (const float*)d_in[14];
    const int* atom_index  = (const int*)d_in[15];
    const int* batch_index = (const int*)d_in[16];
    const int* edge_map    = (const int*)d_in[17];
    float* out = (float*)d_out;

    const int SMEM_RR128 = 2 * (20480 + 128 * 160);  // 81920 (s0)
    const int SMEM_RR64  = 2 * (20480 + 64 * 160);   // 61440 (qkv, final)
    const int SMEM_KK    = 2 * 26624;                // 53248 (out2)
    cudaFuncSetAttribute(qkv_wmma,   cudaFuncAttributeMaxDynamicSharedMemorySize, SMEM_RR64);
    cudaFuncSetAttribute(s0_wmma,    cudaFuncAttributeMaxDynamicSharedMemorySize, SMEM_RR128);
    cudaFuncSetAttribute(final_wmma, cudaFuncAttributeMaxDynamicSharedMemorySize, SMEM_RR64);
    cudaFuncSetAttribute(out2_wmma,  cudaFuncAttributeMaxDynamicSharedMemorySize, SMEM_KK);

    // 1. split all external GEMM operands into hi/lo bf16
    split_kernel<<<dim3(SEG / 1024, 7), 256>>>(q, k, v, Wq, Wk, Wv, Wo);

    // 2. projections (tensor cores, split-bf16), 384 CTAs
    qkv_wmma<<<dim3(HC / 64, NA / 128, 3), 256, SMEM_RR64>>>(bq, bk, bv);

    // 3. EB = exp(attn_bias^T)
    transpose_exp<<<dim3(MM / 64, NA / 64), 256>>>(attn_bias);

    // 4. dense per-atom exp(scores)  [profiled launch, control]
    s0_wmma<<<dim3(NA / 128, NA / 128, NH), 256, SMEM_RR128>>>();

    // 5-6. segment boundaries + CSR
    seg_hist_kernel<<<1, 1024>>>(batch_index, atom_index);
    fill_kernel<<<NA / 8, 256>>>(atom_index);

    // 7-8. softmax denominators + per-atom weights
    csum_kernel<<<dim3(NA / 256, BB), 256>>>(atom_index, edge_map, envelope);
    w2_kernel<<<dim3(NA / 128, NA), 128>>>(edge_map, batch_index, envelope);

    // 9. attention output (tensor cores), K-split x2 -> 256 CTAs
    out2_wmma<<<dim3(HD / 64, NA / 128, NH * 2), 256, SMEM_KK>>>();

    // 10. layernorm (sums partials)
    ln_kernel<<<NA, 256>>>(ln_g, ln_b);

    // 11. final projection (tensor cores), NT=64 + K-split x2 -> 128 CTAs
    final_wmma<<<dim3(INC / 64, NA / 128, 2), 256, SMEM_RR64>>>();

    // 12. combine final partials + bias
    final_combine<<<NA * INC / 1024, 256>>>(bo, out);
}

// round 17
// speedup vs baseline: 1.2518x; 1.0061x over previous
#include <cuda_runtime.h>
#include <cuda_bf16.h>
#include <mma.h>
#include <cstdint>
#include <math.h>

using namespace nvcuda;

// Problem constants
#define NA  1024   // N atoms
#define EE  8192   // E edges
#define MM  8192   // M envelope table
#define BB  64     // B batches
#define INC 512    // IN_CH
#define HC  1024   // H_CH
#define NH  8      // heads
#define HD  128    // head dim

#define SEG 524288 // elements per split slab (all 7 external operands are 512K elems)

// ---------------- scratch ----------------
__device__ __nv_bfloat16 g_split_h[7 * SEG];     // q,k,v,Wq,Wk,Wv,Wo (hi)
__device__ __nv_bfloat16 g_split_l[7 * SEG];     // (lo)
__device__ __nv_bfloat16 g_ph[3 * NA * HC];      // qp/kp/vp hi
__device__ __nv_bfloat16 g_pl[3 * NA * HC];      // qp/kp/vp lo
__device__ __nv_bfloat16 g_lnh[NA * HC];
__device__ __nv_bfloat16 g_lnl[NA * HC];
__device__ __nv_bfloat16 g_W2h[(size_t)NH * NA * NA];
__device__ __nv_bfloat16 g_W2l[(size_t)NH * NA * NA];
__device__ float g_EB[(size_t)MM * NA];          // exp(attn_bias^T)[m][n]
__device__ float g_ES0[(size_t)NH * NA * NA];    // exp(S0)[h][a][n]
__device__ float g_C[BB * NH * NA];
__device__ float g_attn[NA * HC];                // out2 partial (a in [0,512))
__device__ float g_attn2[NA * HC];               // out2 partial (a in [512,1024))
__device__ float g_fpart[2 * NA * INC];          // final partials
__device__ int   g_seg[BB + 1];
__device__ int   g_off[NA + 1];
__device__ int   g_csr[EE];

__device__ __forceinline__ void split2(float v, __nv_bfloat16& h, __nv_bfloat16& l) {
    h = __float2bfloat16(v);
    l = __float2bfloat16(v - __bfloat162float(h));
}

__device__ __forceinline__ uint32_t smem_u32(const void* p) {
    return (uint32_t)__cvta_generic_to_shared(p);
}
__device__ __forceinline__ void cp16(uint32_t dst, const void* src) {
    asm volatile("cp.async.cg.shared.global [%0], [%1], 16;" :: "r"(dst), "l"(src));
}
#define CP_COMMIT asm volatile("cp.async.commit_group;" ::: "memory")

// ---------------- split the 7 external fp32 operands into hi/lo bf16 ----------------
__global__ void __launch_bounds__(256) split_kernel(
    const float* __restrict__ q,  const float* __restrict__ k,  const float* __restrict__ v,
    const float* __restrict__ Wq, const float* __restrict__ Wk, const float* __restrict__ Wv,
    const float* __restrict__ Wo)
{
    const float* srcs[7] = {q, k, v, Wq, Wk, Wv, Wo};
    const float* s = srcs[blockIdx.y];
    const size_t base = (size_t)blockIdx.y * SEG;
    const int i0 = (blockIdx.x * 256 + threadIdx.x) * 4;
    float4 f = *(const float4*)(s + i0);
    union { __nv_bfloat16 b[4]; uint2 u; } H, L;
    split2(f.x, H.b[0], L.b[0]);
    split2(f.y, H.b[1], L.b[1]);
    split2(f.z, H.b[2], L.b[2]);
    split2(f.w, H.b[3], L.b[3]);
    *(uint2*)(g_split_h + base + i0) = H.u;
    *(uint2*)(g_split_l + base + i0) = L.u;
}

// ================= pipelined wmma GEMM cores =================
// Split bf16: C += Ah@Bh^T + Ah@Bl^T + Al@Bh^T  (fp32 accum), K chunk 32, 2 stages.
typedef wmma::fragment<wmma::accumulator, 16, 16, 16, float> FragC;

// ---- rr: A [M,K] row-major (M tile 128), B [N,K] row-major (N tile NT) ----
template<int NT>
__device__ __forceinline__ void rr_load(
    const __nv_bfloat16* __restrict__ Ah, const __nv_bfloat16* __restrict__ Al, int lda, int m0,
    const __nv_bfloat16* __restrict__ Bh, const __nv_bfloat16* __restrict__ Bl, int ldb, int n0,
    int k0, uint32_t stage)
{
    const int tid = threadIdx.x;
#pragma unroll
    for (int rep = 0; rep < 2; rep++) {
        int idx = tid + rep * 256;             // 512 chunks: 128 rows x 4
        int r = idx >> 2, c8 = (idx & 3) * 8;
        uint32_t d = stage + (uint32_t)(r * 40 + c8) * 2;
        size_t off = (size_t)(m0 + r) * lda + k0 + c8;
        cp16(d, Ah + off);
        cp16(d + 10240, Al + off);
    }
#pragma unroll
    for (int rep = 0; rep < NT / 64; rep++) {
        int idx = tid + rep * 256;
        int r = idx >> 2, c8 = (idx & 3) * 8;
        uint32_t d = stage + 20480 + (uint32_t)(r * 40 + c8) * 2;
        size_t off = (size_t)(n0 + r) * ldb + k0 + c8;
        cp16(d, Bh + off);
        cp16(d + NT * 80, Bl + off);
    }
}

template<int NT>
__device__ __forceinline__ void rr_compute(const char* st, FragC (&c)[2][NT / 32])
{
    const int wid = threadIdx.x >> 5;
    const int wm0 = (wid >> 1) * 32;
    const int wn0 = (wid & 1) * (NT / 2);
    const __nv_bfloat16* sAh = (const __nv_bfloat16*)st;
    const __nv_bfloat16* sAl = sAh + 128 * 40;
    const __nv_bfloat16* sBh = (const __nv_bfloat16*)(st + 20480);
    const __nv_bfloat16* sBl = sBh + NT * 40;
    constexpr int FN = NT / 32;
#pragma unroll
    for (int kk = 0; kk < 32; kk += 16) {
        wmma::fragment<wmma::matrix_a, 16, 16, 16, __nv_bfloat16, wmma::row_major> aH[2], aL[2];
        wmma::fragment<wmma::matrix_b, 16, 16, 16, __nv_bfloat16, wmma::col_major> bH[FN], bL[FN];
#pragma unroll
        for (int i = 0; i < 2; i++) {
            wmma::load_matrix_sync(aH[i], sAh + (wm0 + 16 * i) * 40 + kk, 40);
            wmma::load_matrix_sync(aL[i], sAl + (wm0 + 16 * i) * 40 + kk, 40);
        }
#pragma unroll
        for (int j = 0; j < FN; j++) {
            wmma::load_matrix_sync(bH[j], sBh + (wn0 + 16 * j) * 40 + kk, 40);
            wmma::load_matrix_sync(bL[j], sBl + (wn0 + 16 * j) * 40 + kk, 40);
        }
#pragma unroll
        for (int i = 0; i < 2; i++)
#pragma unroll
            for (int j = 0; j < FN; j++) {
                wmma::mma_sync(c[i][j], aH[i], bH[j], c[i][j]);
                wmma::mma_sync(c[i][j], aH[i], bL[j], c[i][j]);
                wmma::mma_sync(c[i][j], aL[i], bH[j], c[i][j]);
            }
    }
}

template<int NT>
__device__ __forceinline__ void gemm_rr_pipe(
    const __nv_bfloat16* Ah, const __nv_bfloat16* Al, int lda, int m0,
    const __nv_bfloat16* Bh, const __nv_bfloat16* Bl, int ldb, int n0,
    int K, char* smem, FragC (&c)[2][NT / 32])
{
    const int SSTR = 20480 + NT * 160;
    uint32_t sb = smem_u32(smem);
#pragma unroll
    for (int i = 0; i < 2; i++)
#pragma unroll
        for (int j = 0; j < NT / 32; j++) wmma::fill_fragment(c[i][j], 0.f);
    rr_load<NT>(Ah, Al, lda, m0, Bh, Bl, ldb, n0, 0, sb);
    CP_COMMIT;
    const int NC = K / 32;
    for (int ch = 0; ch < NC; ch++) {
        if (ch + 1 < NC) {
            rr_load<NT>(Ah, Al, lda, m0, Bh, Bl, ldb, n0, (ch + 1) * 32,
                        sb + ((ch + 1) & 1) * SSTR);
            CP_COMMIT;
            asm volatile("cp.async.wait_group 1;" ::: "memory");
        } else {
            asm volatile("cp.async.wait_group 0;" ::: "memory");
        }
        __syncthreads();
        rr_compute<NT>(smem + (ch & 1) * SSTR, c);
        __syncthreads();
    }
}

// ---- kk: A [K,M] K-major (M tile 128), B [K,N] K-major (N tile 64) ----
__device__ __forceinline__ void kk_load(
    const __nv_bfloat16* __restrict__ Ah, const __nv_bfloat16* __restrict__ Al, int lda, int m0,
    const __nv_bfloat16* __restrict__ Bh, const __nv_bfloat16* __restrict__ Bl, int ldb, int n0,
    int k0, uint32_t stage)
{
    const int tid = threadIdx.x;
#pragma unroll
    for (int rep = 0; rep < 2; rep++) {
        int idx = tid + rep * 256;              // 512 chunks: 32 rows x 16
        int r = idx >> 4, c8 = (idx & 15) * 8;
        uint32_t d = stage + (uint32_t)(r * 136 + c8) * 2;
        size_t off = (size_t)(k0 + r) * lda + m0 + c8;
        cp16(d, Ah + off);
        cp16(d + 8704, Al + off);
    }
    {
        int r = tid >> 3, c8 = (tid & 7) * 8;   // 256 chunks: 32 rows x 8
        uint32_t d = stage + 17408 + (uint32_t)(r * 72 + c8) * 2;
        size_t off = (size_t)(k0 + r) * ldb + n0 + c8;
        cp16(d, Bh + off);
        cp16(d + 4608, Bl + off);
    }
}

__device__ __forceinline__ void kk_compute(const char* st, FragC (&c)[2][2])
{
    const int wid = threadIdx.x >> 5;
    const int wm0 = (wid >> 1) * 32;
    const int wn0 = (wid & 1) * 32;
    const __nv_bfloat16* sAh = (const __nv_bfloat16*)st;
    const __nv_bfloat16* sAl = sAh + 32 * 136;
    const __nv_bfloat16* sBh = (const __nv_bfloat16*)(st + 17408);
    const __nv_bfloat16* sBl = sBh + 32 * 72;
#pragma unroll
    for (int kk = 0; kk < 32; kk += 16) {
        wmma::fragment<wmma::matrix_a, 16, 16, 16, __nv_bfloat16, wmma::col_major> aH[2], aL[2];
        wmma::fragment<wmma::matrix_b, 16, 16, 16, __nv_bfloat16, wmma::row_major> bH[2], bL[2];
#pragma unroll
        for (int i = 0; i < 2; i++) {
            wmma::load_matrix_sync(aH[i], sAh + kk * 136 + wm0 + 16 * i, 136);
            wmma::load_matrix_sync(aL[i], sAl + kk * 136 + wm0 + 16 * i, 136);
        }
#pragma unroll
        for (int j = 0; j < 2; j++) {
            wmma::load_matrix_sync(bH[j], sBh + kk * 72 + wn0 + 16 * j, 72);
            wmma::load_matrix_sync(bL[j], sBl + kk * 72 + wn0 + 16 * j, 72);
        }
#pragma unroll
        for (int i = 0; i < 2; i++)
#pragma unroll
            for (int j = 0; j < 2; j++) {
                wmma::mma_sync(c[i][j], aH[i], bH[j], c[i][j]);
                wmma::mma_sync(c[i][j], aH[i], bL[j], c[i][j]);
                wmma::mma_sync(c[i][j], aL[i], bH[j], c[i][j]);
            }
    }
}

__device__ __forceinline__ void gemm_kk_pipe(
    const __nv_bfloat16* Ah, const __nv_bfloat16* Al, int lda, int m0,
    const __nv_bfloat16* Bh, const __nv_bfloat16* Bl, int ldb, int n0,
    int K, char* smem, FragC (&c)[2][2])
{
    const int SSTR = 26624;
    uint32_t sb = smem_u32(smem);
#pragma unroll
    for (int i = 0; i < 2; i++)
#pragma unroll
        for (int j = 0; j < 2; j++) wmma::fill_fragment(c[i][j], 0.f);
    kk_load(Ah, Al, lda, m0, Bh, Bl, ldb, n0, 0, sb);
    CP_COMMIT;
    const int NC = K / 32;
    for (int ch = 0; ch < NC; ch++) {
        if (ch + 1 < NC) {
            kk_load(Ah, Al, lda, m0, Bh, Bl, ldb, n0, (ch + 1) * 32,
                    sb + ((ch + 1) & 1) * SSTR);
            CP_COMMIT;
            asm volatile("cp.async.wait_group 1;" ::: "memory");
        } else {
            asm volatile("cp.async.wait_group 0;" ::: "memory");
        }
        __syncthreads();
        kk_compute(smem + (ch & 1) * SSTR, c);
        __syncthreads();
    }
}

// epilogue scratch overlay: per warp 32 x (WN+4) floats on top of pipeline smem
template<int WN, int FN>
__device__ __forceinline__ float* epi_store(FragC (&c)[2][FN], char* smem, int wid)
{
    float* sC = (float*)smem + wid * 32 * (WN + 4);
#pragma unroll
    for (int i = 0; i < 2; i++)
#pragma unroll
        for (int j = 0; j < FN; j++)
            wmma::store_matrix_sync(sC + i * 16 * (WN + 4) + j * 16, c[i][j],
                                    WN + 4, wmma::mem_row_major);
    __syncwarp();
    return sC;
}

// ---- qkv (NT=64): proj_z[atom][hc] = in_z @ W_z^T + b_z, written as hi/lo bf16 ----
__global__ void __launch_bounds__(256, 2) qkv_wmma(
    const float* __restrict__ bq, const float* __restrict__ bk, const float* __restrict__ bv)
{
    extern __shared__ char smem[];
    const int tid = threadIdx.x, wid = tid >> 5, lane = tid & 31;
    const int z  = blockIdx.z;
    const int m0 = blockIdx.y * 128;   // atom
    const int n0 = blockIdx.x * 64;    // hc
    const float* bias = (z == 0) ? bq : (z == 1) ? bk : bv;
    FragC c[2][2];
    gemm_rr_pipe<64>(g_split_h + (size_t)z * SEG,       g_split_l + (size_t)z * SEG,       INC, m0,
                     g_split_h + (size_t)(3 + z) * SEG, g_split_l + (size_t)(3 + z) * SEG, INC, n0,
                     INC, smem, c);
    float* sC = epi_store<32, 2>(c, smem, wid);
    const int wm0 = (wid >> 1) * 32, wn0 = (wid & 1) * 32;
    const int atom = m0 + wm0 + lane;
    const size_t ob = (size_t)z * NA * HC + (size_t)atom * HC + n0 + wn0;
    union { __nv_bfloat16 b[8]; uint4 u; } H, L;
#pragma unroll
    for (int t = 0; t < 4; t++) {
#pragma unroll
        for (int e = 0; e < 8; e++) {
            float val = sC[lane * 36 + t * 8 + e] + bias[n0 + wn0 + t * 8 + e];
            split2(val, H.b[e], L.b[e]);
        }
        *(uint4*)(g_ph + ob + t * 8) = H.u;
        *(uint4*)(g_pl + ob + t * 8) = L.u;
    }
}

// ---- s0 SINGLE-SHOT (K=128 fits in smem): ES0[h][a][n] = exp(dot(kp_a,qp_n)/sqrt(D))
// smem: Ah[128][136] @0, Al @34816, Bh[64][136] @69632, Bl @87040; total 104448
__global__ void __launch_bounds__(256, 2) s0_wmma()
{
    extern __shared__ char smem[];
    const int tid = threadIdx.x, wid = tid >> 5, lane = tid & 31;
    const int h  = blockIdx.z;
    const int m0 = blockIdx.y * 128;   // a (A operand = kp)
    const int n0 = blockIdx.x * 64;    // n (B operand = qp)
    const __nv_bfloat16* Ah = g_ph + 1 * NA * HC + h * HD;
    const __nv_bfloat16* Al = g_pl + 1 * NA * HC + h * HD;
    const __nv_bfloat16* Bh = g_ph + 0 * NA * HC + h * HD;
    const __nv_bfloat16* Bl = g_pl + 0 * NA * HC + h * HD;
    uint32_t sb = smem_u32(smem);

    // one bulk load of the whole K=128 extent
#pragma unroll
    for (int rep = 0; rep < 8; rep++) {
        int idx = tid + rep * 256;             // 2048 chunks: 128 rows x 16
        int r = idx >> 4, c8 = (idx & 15) * 8;
        uint32_t d = sb + (uint32_t)(r * 136 + c8) * 2;
        size_t off = (size_t)(m0 + r) * HC + c8;
        cp16(d, Ah + off);
        cp16(d + 34816, Al + off);
    }
#pragma unroll
    for (int rep = 0; rep < 4; rep++) {
        int idx = tid + rep * 256;             // 1024 chunks: 64 rows x 16
        int r = idx >> 4, c8 = (idx & 15) * 8;
        uint32_t d = sb + 69632 + (uint32_t)(r * 136 + c8) * 2;
        size_t off = (size_t)(n0 + r) * HC + c8;
        cp16(d, Bh + off);
        cp16(d + 17408, Bl + off);
    }
    CP_COMMIT;
    asm volatile("cp.async.wait_group 0;" ::: "memory");
    __syncthreads();

    const __nv_bfloat16* sAh = (const __nv_bfloat16*)smem;
    const __nv_bfloat16* sAl = (const __nv_bfloat16*)(smem + 34816);
    const __nv_bfloat16* sBh = (const __nv_bfloat16*)(smem + 69632);
    const __nv_bfloat16* sBl = (const __nv_bfloat16*)(smem + 87040);
    const int wm0 = (wid >> 1) * 32, wn0 = (wid & 1) * 32;
    FragC c[2][2];
#pragma unroll
    for (int i = 0; i < 2; i++)
#pragma unroll
        for (int j = 0; j < 2; j++) wmma::fill_fragment(c[i][j], 0.f);

    // all 8 k-steps, fully unrolled, no barriers
#pragma unroll
    for (int kk = 0; kk < 128; kk += 16) {
        wmma::fragment<wmma::matrix_a, 16, 16, 16, __nv_bfloat16, wmma::row_major> aH[2], aL[2];
        wmma::fragment<wmma::matrix_b, 16, 16, 16, __nv_bfloat16, wmma::col_major> bH[2], bL[2];
#pragma unroll
        for (int i = 0; i < 2; i++) {
            wmma::load_matrix_sync(aH[i], sAh + (wm0 + 16 * i) * 136 + kk, 136);
            wmma::load_matrix_sync(aL[i], sAl + (wm0 + 16 * i) * 136 + kk, 136);
        }
#pragma unroll
        for (int j = 0; j < 2; j++) {
            wmma::load_matrix_sync(bH[j], sBh + (wn0 + 16 * j) * 136 + kk, 136);
            wmma::load_matrix_sync(bL[j], sBl + (wn0 + 16 * j) * 136 + kk, 136);
        }
#pragma unroll
        for (int i = 0; i < 2; i++)
#pragma unroll
            for (int j = 0; j < 2; j++) {
                wmma::mma_sync(c[i][j], aH[i], bH[j], c[i][j]);
                wmma::mma_sync(c[i][j], aH[i], bL[j], c[i][j]);
                wmma::mma_sync(c[i][j], aL[i], bH[j], c[i][j]);
            }
    }
    __syncthreads();   // before overwriting smem with epilogue scratch

    float* sC = epi_store<32, 2>(c, smem, wid);
    const int a = m0 + wm0 + lane;
    const float scale = 0.08838834764831845f;   // 1/sqrt(128)
    float* dst = g_ES0 + ((size_t)h * NA + a) * NA + n0 + wn0;
#pragma unroll
    for (int t = 0; t < 8; t++) {
        float4 r;
        r.x = __expf(sC[lane * 36 + t * 4 + 0] * scale);
        r.y = __expf(sC[lane * 36 + t * 4 + 1] * scale);
        r.z = __expf(sC[lane * 36 + t * 4 + 2] * scale);
        r.w = __expf(sC[lane * 36 + t * 4 + 3] * scale);
        *(float4*)(dst + t * 4) = r;
    }
}

// ---- out2 (K-split x2): partial[n][h*HD+d] = sum_{a in half} W2[h][a][n]*vp[a][h*HD+d]
__global__ void __launch_bounds__(256, 2) out2_wmma()
{
    extern __shared__ char smem[];
    const int tid = threadIdx.x, wid = tid >> 5, lane = tid & 31;
    const int h    = blockIdx.z & 7;
    const int half = blockIdx.z >> 3;
    const int m0 = blockIdx.y * 128;   // n
    const int n0 = blockIdx.x * 64;    // d
    const size_t koff = (size_t)half * 512;
    FragC c[2][2];
    gemm_kk_pipe(g_W2h + (size_t)h * NA * NA + koff * NA,
                 g_W2l + (size_t)h * NA * NA + koff * NA, NA, m0,
                 g_ph + 2 * NA * HC + h * HD + koff * HC,
                 g_pl + 2 * NA * HC + h * HD + koff * HC, HC, n0,
                 512, smem, c);
    float* sC = epi_store<32, 2>(c, smem, wid);
    const int wm0 = (wid >> 1) * 32, wn0 = (wid & 1) * 32;
    const int n = m0 + wm0 + lane;
    float* base = half ? g_attn2 : g_attn;
    float* dst = base + (size_t)n * HC + h * HD + n0 + wn0;
#pragma unroll
    for (int t = 0; t < 8; t++) {
        float4 r;
        r.x = sC[lane * 36 + t * 4 + 0];
        r.y = sC[lane * 36 + t * 4 + 1];
        r.z = sC[lane * 36 + t * 4 + 2];
        r.w = sC[lane * 36 + t * 4 + 3];
        *(float4*)(dst + t * 4) = r;
    }
}

// ---- final (NT=64, K-split x2): partial = ln @ Wo^T over half of HC ----
__global__ void __launch_bounds__(256, 2) final_wmma()
{
    extern __shared__ char smem[];
    const int tid = threadIdx.x, wid = tid >> 5, lane = tid & 31;
    const int half = blockIdx.z;
    const int m0 = blockIdx.y * 128;   // n
    const int n0 = blockIdx.x * 64;    // ic
    const int koff = half * 512;
    FragC c[2][2];
    gemm_rr_pipe<64>(g_lnh + koff, g_lnl + koff, HC, m0,
                     g_split_h + 6 * SEG + koff, g_split_l + 6 * SEG + koff, HC, n0,
                     512, smem, c);
    float* sC = epi_store<32, 2>(c, smem, wid);
    const int wm0 = (wid >> 1) * 32, wn0 = (wid & 1) * 32;
    const int n = m0 + wm0 + lane;
    float* dst = g_fpart + (size_t)half * NA * INC + (size_t)n * INC + n0 + wn0;
#pragma unroll
    for (int t = 0; t < 8; t++) {
        float4 r;
        r.x = sC[lane * 36 + t * 4 + 0];
        r.y = sC[lane * 36 + t * 4 + 1];
        r.z = sC[lane * 36 + t * 4 + 2];
        r.w = sC[lane * 36 + t * 4 + 3];
        *(float4*)(dst + t * 4) = r;
    }
}

// ---- final combine: out = p0 + p1 + bo ----
__global__ void __launch_bounds__(256) final_combine(
    const float* __restrict__ bo, float* __restrict__ out)
{
    const int i4 = (blockIdx.x * 256 + threadIdx.x) * 4;
    float4 a = *(const float4*)(g_fpart + i4);
    float4 b = *(const float4*)(g_fpart + NA * INC + i4);
    float4 bb = *(const float4*)(bo + (i4 & (INC - 1)));
    float4 r;
    r.x = a.x + b.x + bb.x;
    r.y = a.y + b.y + bb.y;
    r.z = a.z + b.z + bb.z;
    r.w = a.w + b.w + bb.w;
    *(float4*)(out + i4) = r;
}

// ---------------- EB[m][n] = exp(attn_bias[n][m]) ----------------
__global__ void __launch_bounds__(256) transpose_exp(const float* __restrict__ src)
{
    __shared__ float tile[64][65];
    const int m0 = blockIdx.x * 64, n0 = blockIdx.y * 64;
    const int tid = threadIdx.x;
    const int r = tid >> 4, c4 = (tid & 15) * 4;
#pragma unroll
    for (int p = 0; p < 4; p++) {
        float4 vld = *(const float4*)(src + (size_t)(n0 + r + p * 16) * MM + m0 + c4);
        tile[r + p * 16][c4 + 0] = vld.x;
        tile[r + p * 16][c4 + 1] = vld.y;
        tile[r + p * 16][c4 + 2] = vld.z;
        tile[r + p * 16][c4 + 3] = vld.w;
    }
    __syncthreads();
#pragma unroll
    for (int p = 0; p < 4; p++) {
        const int mloc = r + p * 16;
        float4 o;
        o.x = __expf(tile[c4 + 0][mloc]);
        o.y = __expf(tile[c4 + 1][mloc]);
        o.z = __expf(tile[c4 + 2][mloc]);
        o.w = __expf(tile[c4 + 3][mloc]);
        *(float4*)(g_EB + (size_t)(m0 + mloc) * NA + n0 + c4) = o;
    }
}

// ---------------- seg (binary search) + CSR histogram/scan, fused, 1 CTA ------------
__global__ void __launch_bounds__(1024) seg_hist_kernel(
    const int* __restrict__ batch_index, const int* __restrict__ atom_index)
{
    __shared__ int buf[1024];
    const int tid = threadIdx.x;
    if (tid <= BB) {
        int lo = 0, hi = EE;
        while (lo < hi) {
            int mid = (lo + hi) >> 1;
            if (batch_index[mid] < tid) lo = mid + 1; else hi = mid;
        }
        g_seg[tid] = lo;
    }
    buf[tid] = 0;
    __syncthreads();
#pragma unroll
    for (int i = 0; i < EE / 1024; i++)
        atomicAdd(&buf[atom_index[tid + i * 1024]], 1);
    __syncthreads();
    for (int s = 1; s < 1024; s <<= 1) {
        int v = (tid >= s) ? buf[tid - s] : 0;
        __syncthreads();
        buf[tid] += v;
        __syncthreads();
    }
    g_off[tid + 1] = buf[tid];
    if (tid == 0) g_off[0] = 0;
}

__global__ void __launch_bounds__(256) fill_kernel(const int* __restrict__ atom_index)
{
    const int w = (blockIdx.x * 256 + threadIdx.x) >> 5;
    const int lane = threadIdx.x & 31;
    int o = g_off[w];
    for (int base = 0; base < EE; base += 32) {
        int a = atom_index[base + lane];
        bool match = (a == w);
        unsigned mask = __ballot_sync(0xffffffffu, match);
        int rank = __popc(mask & ((1u << lane) - 1));
        if (match) g_csr[o + rank] = base + lane;
        o += __popc(mask);
    }
}

// ---- C[b][h][n] = 1 / (sum_{e in b} env_e * EB[mp_e][n] * ES0[h][a_e][n] + 1e-16) ----
__global__ void __launch_bounds__(256) csum_kernel(
    const int* __restrict__ atom_index, const int* __restrict__ edge_map,
    const float* __restrict__ envelope)
{
    const int b = blockIdx.y;
    const int n = blockIdx.x * 256 + threadIdx.x;
    const int s0 = g_seg[b], s1 = g_seg[b + 1];
    __shared__ int   s_a[128], s_mp[128];
    __shared__ float s_env[128];
    float acc[NH] = {};
    for (int c = s0; c < s1; c += 128) {
        const int cnt = min(128, s1 - c);
        __syncthreads();
        if (threadIdx.x < cnt) {
            int e = c + threadIdx.x;
            int mp = edge_map[e];
            s_a[threadIdx.x]   = atom_index[e];
            s_mp[threadIdx.x]  = mp;
            s_env[threadIdx.x] = envelope[mp];
        }
        __syncthreads();
        for (int i = 0; i < cnt; i++) {
            float val = s_env[i] * g_EB[(size_t)s_mp[i] * NA + n];
            const float* es = g_ES0 + (size_t)s_a[i] * NA + n;
#pragma unroll
            for (int h = 0; h < NH; h++)
                acc[h] += val * es[(size_t)h * NA * NA];
        }
    }
#pragma unroll
    for (int h = 0; h < NH; h++)
        g_C[((size_t)b * NH + h) * NA + n] = 1.f / (acc[h] + 1e-16f);
}

// ---- W2[h][a][n] = ES0[h][a][n] * sum_{e->a} env_e^2 * EB[mp_e][n] * C[b_e][h][n] ----
__global__ void __launch_bounds__(128) w2_kernel(
    const int* __restrict__ edge_map, const int* __restrict__ batch_index,
    const float* __restrict__ envelope)
{
    const int a = blockIdx.y;
    const int n = blockIdx.x * 128 + threadIdx.x;
    const int o0 = g_off[a], o1 = g_off[a + 1];
    float acc[NH] = {};
    for (int j = o0; j < o1; j++) {
        int e  = g_csr[j];
        int mp = edge_map[e];
        int bb = batch_index[e];
        float env = envelope[mp];
        float t = env * env * g_EB[(size_t)mp * NA + n];
        const float* Cb = g_C + (size_t)bb * NH * NA + n;
#pragma unroll
        for (int h = 0; h < NH; h++)
            acc[h] += t * Cb[(size_t)h * NA];
    }
#pragma unroll
    for (int h = 0; h < NH; h++) {
        const size_t idx = ((size_t)h * NA + a) * NA + n;
        float val = g_ES0[idx] * acc[h];
        split2(val, g_W2h[idx], g_W2l[idx]);
    }
}

// ---------------- LayerNorm (sums the two out2 partials) -> hi/lo bf16 ----------------
__global__ void __launch_bounds__(256) ln_kernel(
    const float* __restrict__ ln_g, const float* __restrict__ ln_b)
{
    const int n = blockIdx.x;
    const int tid = threadIdx.x;
    const float* x0 = g_attn  + (size_t)n * HC;
    const float* x1 = g_attn2 + (size_t)n * HC;
    float s = 0.f, s2 = 0.f;
    for (int i = tid; i < HC; i += 256) {
        float v = x0[i] + x1[i];
        s += v; s2 += v * v;
    }
#pragma unroll
    for (int o = 16; o > 0; o >>= 1) {
        s  += __shfl_xor_sync(0xffffffffu, s, o);
        s2 += __shfl_xor_sync(0xffffffffu, s2, o);
    }
    __shared__ float ws[8], ws2[8], stats[2];
    if ((tid & 31) == 0) { ws[tid >> 5] = s; ws2[tid >> 5] = s2; }
    __syncthreads();
    if (tid == 0) {
        float a = 0.f, b = 0.f;
#pragma unroll
        for (int i = 0; i < 8; i++) { a += ws[i]; b += ws2[i]; }
        float mean = a * (1.f / HC);
        float var  = b * (1.f / HC) - mean * mean;
        stats[0] = mean;
        stats[1] = rsqrtf(var + 1e-7f);
    }
    __syncthreads();
    const float mean = stats[0], inv = stats[1];
    for (int i = tid; i < HC; i += 256) {
        float val = (x0[i] + x1[i] - mean) * inv * ln_g[i] + ln_b[i];
        split2(val, g_lnh[(size_t)n * HC + i], g_lnl[(size_t)n * HC + i]);
    }
}

// ---------------- launch ----------------
extern "C" void kernel_launch(void* const* d_in, const int* in_sizes, int n_in,
                              void* d_out, int out_size)
{
    const float* q         = (const float*)d_in[0];
    const float* k         = (const float*)d_in[1];
    const float* v         = (const float*)d_in[2];
    const float* envelope  = (const float*)d_in[3];
    const float* attn_bias = (const float*)d_in[4];
    const float* Wq        = (const float*)d_in[5];
    const float* bq        = (const float*)d_in[6];
    const float* Wk        = (const float*)d_in[7];
    const float* bk        = (const float*)d_in[8];
    const float* Wv        = (const float*)d_in[9];
    const float* bv        = (const float*)d_in[10];
    const float* ln_g      = (const float*)d_in[11];
    const float* ln_b      = (const float*)d_in[12];
    const float* Wo        = (const float*)d_in[13];
    const float* bo        = (const float*)d_in[14];
    const int* atom_index  = (const int*)d_in[15];
    const int* batch_index = (const int*)d_in[16];
    const int* edge_map    = (const int*)d_in[17];
    float* out = (float*)d_out;

    const int SMEM_S0    = 104448;                   // single-shot s0
    const int SMEM_RR64  = 2 * (20480 + 64 * 160);   // 61440 (qkv, final)
    const int SMEM_KK    = 2 * 26624;                // 53248 (out2)
    cudaFuncSetAttribute(qkv_wmma,   cudaFuncAttributeMaxDynamicSharedMemorySize, SMEM_RR64);
    cudaFuncSetAttribute(s0_wmma,    cudaFuncAttributeMaxDynamicSharedMemorySize, SMEM_S0);
    cudaFuncSetAttribute(final_wmma, cudaFuncAttributeMaxDynamicSharedMemorySize, SMEM_RR64);
    cudaFuncSetAttribute(out2_wmma,  cudaFuncAttributeMaxDynamicSharedMemorySize, SMEM_KK);

    // 1. split all external GEMM operands into hi/lo bf16
    split_kernel<<<dim3(SEG / 1024, 7), 256>>>(q, k, v, Wq, Wk, Wv, Wo);

    // 2. projections (tensor cores, split-bf16), 384 CTAs
    qkv_wmma<<<dim3(HC / 64, NA / 128, 3), 256, SMEM_RR64>>>(bq, bk, bv);

    // 3. EB = exp(attn_bias^T)
    transpose_exp<<<dim3(MM / 64, NA / 64), 256>>>(attn_bias);

    // 4. dense per-atom exp(scores), single-shot K  [profiled launch]
    s0_wmma<<<dim3(NA / 64, NA / 128, NH), 256, SMEM_S0>>>();

    // 5-6. segment boundaries + CSR
    seg_hist_kernel<<<1, 1024>>>(batch_index, atom_index);
    fill_kernel<<<NA / 8, 256>>>(atom_index);

    // 7-8. softmax denominators + per-atom weights
    csum_kernel<<<dim3(NA / 256, BB), 256>>>(atom_index, edge_map, envelope);
    w2_kernel<<<dim3(NA / 128, NA), 128>>>(edge_map, batch_index, envelope);

    // 9. attention output (tensor cores), K-split x2 -> 256 CTAs
    out2_wmma<<<dim3(HD / 64, NA / 128, NH * 2), 256, SMEM_KK>>>();

    // 10. layernorm (sums partials)
    ln_kernel<<<NA, 256>>>(ln_g, ln_b);

    // 11. final projection (tensor cores), NT=64 + K-split x2 -> 128 CTAs
    final_wmma<<<dim3(INC / 64, NA / 128, 2), 256, SMEM_RR64>>>();

    // 12. combine final partials + bias
    final_combine<<<NA * INC / 1024, 256>>>(bo, out);
}